// round 1
// baseline (speedup 1.0000x reference)
#include <cuda_runtime.h>
#include <cstdint>

// Problem constants (B=2, H=16, S=2048, D=64)
#define BATCH 2
#define HEADS 16
#define BH    (BATCH * HEADS)   // 32
#define SEQ   2048
#define HDIM  64
#define TQ    64                // query tile
#define TK    64                // key tile
#define NQT   (SEQ / TQ)        // 32 query tiles
#define NKT   (SEQ / TK)        // 32 key tiles

// Scratch: per-row softmax denominators (sum of exp(s)), written by pass A.
__device__ float g_l[BH * SEQ];

// ---------------------------------------------------------------------------
// Pass A: scores = (q/8)·k^T over the causal lower triangle.
// Writes e = exp(s) (masked -> 0) directly into the attn output region
// (unnormalized), and row sums l into g_l.
// Block: 256 threads as 16x16, each thread owns a 4x4 micro-tile.
// Grid: (qt, bh)
// ---------------------------------------------------------------------------
__global__ __launch_bounds__(256)
void attn_scores_kernel(const float* __restrict__ q,
                        const float* __restrict__ k,
                        const int*   __restrict__ mask,
                        float*       __restrict__ attn)
{
    const int qt  = blockIdx.x;
    const int bh  = blockIdx.y;
    const int b   = bh >> 4;              // H = 16
    const int tid = threadIdx.x;
    const int tx  = tid & 15;
    const int ty  = tid >> 4;
    const int tx4 = tx * 4;
    const int ty4 = ty * 4;

    __shared__ float qs[TQ][HDIM + 1];
    __shared__ float ks[TK][HDIM + 1];
    __shared__ float lpart[TQ][17];

    // Load q tile (pre-scaled by 1/temperature = 0.125)
    const float* qbase = q + ((size_t)bh * SEQ + (size_t)qt * TQ) * HDIM;
    #pragma unroll
    for (int i = tid; i < TQ * HDIM; i += 256) {
        int r = i >> 6, d = i & 63;
        qs[r][d] = qbase[r * HDIM + d] * 0.125f;
    }

    float* attnrow = attn + (size_t)bh * SEQ * SEQ + (size_t)qt * TQ * SEQ;
    const int* mrow = mask + b * SEQ;

    float rowsum[4] = {0.f, 0.f, 0.f, 0.f};

    for (int kt = 0; kt <= qt; ++kt) {
        __syncthreads();  // previous GEMM done before overwriting ks
        const float* kbase = k + ((size_t)bh * SEQ + (size_t)kt * TK) * HDIM;
        #pragma unroll
        for (int i = tid; i < TK * HDIM; i += 256) {
            int r = i >> 6, d = i & 63;
            ks[r][d] = kbase[r * HDIM + d];
        }
        __syncthreads();

        float acc[4][4] = {};
        #pragma unroll 16
        for (int d = 0; d < HDIM; ++d) {
            float a[4], bb[4];
            #pragma unroll
            for (int i = 0; i < 4; ++i) a[i]  = qs[ty4 + i][d];
            #pragma unroll
            for (int j = 0; j < 4; ++j) bb[j] = ks[tx4 + j][d];
            #pragma unroll
            for (int i = 0; i < 4; ++i)
                #pragma unroll
                for (int j = 0; j < 4; ++j)
                    acc[i][j] += a[i] * bb[j];
        }

        // Epilogue: mask (padding + causal), exp, store e, accumulate row sums
        const int col0 = kt * TK + tx4;
        const int m0 = mrow[col0 + 0];
        const int m1 = mrow[col0 + 1];
        const int m2 = mrow[col0 + 2];
        const int m3 = mrow[col0 + 3];

        #pragma unroll
        for (int i = 0; i < 4; ++i) {
            const int grow = qt * TQ + ty4 + i;
            float4 e;
            e.x = (m0 != 0 && (col0 + 0) <= grow) ? __expf(acc[i][0]) : 0.f;
            e.y = (m1 != 0 && (col0 + 1) <= grow) ? __expf(acc[i][1]) : 0.f;
            e.z = (m2 != 0 && (col0 + 2) <= grow) ? __expf(acc[i][2]) : 0.f;
            e.w = (m3 != 0 && (col0 + 3) <= grow) ? __expf(acc[i][3]) : 0.f;
            rowsum[i] += e.x + e.y + e.z + e.w;
            *reinterpret_cast<float4*>(&attnrow[(size_t)(ty4 + i) * SEQ + col0]) = e;
        }
    }

    // Reduce row sums across tx and write l
    #pragma unroll
    for (int i = 0; i < 4; ++i) lpart[ty4 + i][tx] = rowsum[i];
    __syncthreads();
    if (tid < TQ) {
        float s = 0.f;
        #pragma unroll
        for (int t = 0; t < 16; ++t) s += lpart[tid][t];
        g_l[bh * SEQ + qt * TQ + tid] = s;
    }
}

// ---------------------------------------------------------------------------
// Pass B: p = e / l (in-place in attn), out = p @ v, zero upper triangle.
// Grid: (qt, bh), 256 threads, 4x4 micro-tiles for out (TQ x HDIM).
// ---------------------------------------------------------------------------
__global__ __launch_bounds__(256)
void attn_av_kernel(const float* __restrict__ v,
                    float*       __restrict__ attn,
                    float*       __restrict__ out)
{
    const int qt  = blockIdx.x;
    const int bh  = blockIdx.y;
    const int tid = threadIdx.x;
    const int tx  = tid & 15;
    const int ty  = tid >> 4;
    const int tx4 = tx * 4;
    const int ty4 = ty * 4;

    __shared__ float es[TQ][TK + 4];      // stride 68 keeps float4 alignment
    __shared__ float vs[TK][HDIM + 1];
    __shared__ float invl[TQ];

    if (tid < TQ) invl[tid] = 1.0f / g_l[bh * SEQ + qt * TQ + tid];

    float* attnrow = attn + (size_t)bh * SEQ * SEQ + (size_t)qt * TQ * SEQ;

    float acc[4][4] = {};

    for (int kt = 0; kt <= qt; ++kt) {
        __syncthreads();  // previous GEMM done (also covers invl on first iter)

        // Load e tile, scale to p, write p back, stage p in smem.
        #pragma unroll
        for (int i = tid; i < TQ * TK / 4; i += 256) {
            int r  = i >> 4;
            int c0 = (i & 15) * 4;
            float4 e = *reinterpret_cast<const float4*>(
                &attnrow[(size_t)r * SEQ + kt * TK + c0]);
            float il = invl[r];
            e.x *= il; e.y *= il; e.z *= il; e.w *= il;
            *reinterpret_cast<float4*>(&attnrow[(size_t)r * SEQ + kt * TK + c0]) = e;
            *reinterpret_cast<float4*>(&es[r][c0]) = e;
        }
        // Load v tile
        const float* vbase = v + ((size_t)bh * SEQ + (size_t)kt * TK) * HDIM;
        #pragma unroll
        for (int i = tid; i < TK * HDIM; i += 256) {
            int r = i >> 6, d = i & 63;
            vs[r][d] = vbase[r * HDIM + d];
        }
        __syncthreads();

        // out[r][dc] += p[r][j] * v[j][dc]
        #pragma unroll 16
        for (int j = 0; j < TK; ++j) {
            float a[4], bb[4];
            #pragma unroll
            for (int i = 0; i < 4; ++i)  a[i]  = es[ty4 + i][j];
            #pragma unroll
            for (int jj = 0; jj < 4; ++jj) bb[jj] = vs[j][tx4 + jj];
            #pragma unroll
            for (int i = 0; i < 4; ++i)
                #pragma unroll
                for (int jj = 0; jj < 4; ++jj)
                    acc[i][jj] += a[i] * bb[jj];
        }
    }

    // Zero the strictly-upper tiles of this block row (attn must be fully written)
    for (int kt = qt + 1; kt < NKT; ++kt) {
        const float4 z = {0.f, 0.f, 0.f, 0.f};
        #pragma unroll
        for (int i = tid; i < TQ * TK / 4; i += 256) {
            int r  = i >> 4;
            int c0 = (i & 15) * 4;
            *reinterpret_cast<float4*>(&attnrow[(size_t)r * SEQ + kt * TK + c0]) = z;
        }
    }

    // Write out tile
    float* obase = out + ((size_t)bh * SEQ + (size_t)qt * TQ) * HDIM;
    #pragma unroll
    for (int i = 0; i < 4; ++i) {
        float4 o;
        o.x = acc[i][0]; o.y = acc[i][1]; o.z = acc[i][2]; o.w = acc[i][3];
        *reinterpret_cast<float4*>(&obase[(size_t)(ty4 + i) * HDIM + tx4]) = o;
    }
}

// ---------------------------------------------------------------------------
extern "C" void kernel_launch(void* const* d_in, const int* in_sizes, int n_in,
                              void* d_out, int out_size)
{
    const float* q    = (const float*)d_in[0];
    const float* k    = (const float*)d_in[1];
    const float* v    = (const float*)d_in[2];
    const int*   mask = (const int*)d_in[3];

    float* out  = (float*)d_out;                       // [B,H,S,D]
    float* attn = out + (size_t)BH * SEQ * HDIM;       // [B,H,S,S]

    dim3 grid(NQT, BH);
    attn_scores_kernel<<<grid, 256>>>(q, k, mask, attn);
    attn_av_kernel<<<grid, 256>>>(v, attn, out);
}

// round 3
// speedup vs baseline: 1.4474x; 1.4474x over previous
#include <cuda_runtime.h>
#include <cuda_bf16.h>
#include <cstdint>

// B=2,H=16,S=2048,D=64 fp32 causal attention; d_out = out[B,H,S,D] ++ attn[B,H,S,S]
#define SEQ   2048
#define HDIM  64
#define BH    32
#define TILE  128
#define NT    (SEQ / TILE)   // 16

__device__ float g_l[BH * SEQ];   // softmax denominators

// ---------------------------------------------------------------------------
__device__ __forceinline__ uint32_t smem_u32(const void* p) {
    uint32_t a;
    asm("{ .reg .u64 t; cvta.to.shared.u64 t, %1; cvt.u32.u64 %0, t; }" : "=r"(a) : "l"(p));
    return a;
}
__device__ __forceinline__ void ldsm_x4(uint32_t* r, uint32_t a) {
    asm volatile("ldmatrix.sync.aligned.m8n8.x4.shared.b16 {%0,%1,%2,%3}, [%4];"
        : "=r"(r[0]), "=r"(r[1]), "=r"(r[2]), "=r"(r[3]) : "r"(a));
}
__device__ __forceinline__ void ldsm_x2(uint32_t* r, uint32_t a) {
    asm volatile("ldmatrix.sync.aligned.m8n8.x2.shared.b16 {%0,%1}, [%2];"
        : "=r"(r[0]), "=r"(r[1]) : "r"(a));
}
__device__ __forceinline__ void ldsm_x2t(uint32_t* r, uint32_t a) {
    asm volatile("ldmatrix.sync.aligned.m8n8.x2.trans.shared.b16 {%0,%1}, [%2];"
        : "=r"(r[0]), "=r"(r[1]) : "r"(a));
}
// D += A * B  (m16n8k16, bf16 in, fp32 accum)
__device__ __forceinline__ void mma16816(float* c, const uint32_t* a, const uint32_t* b) {
    asm volatile("mma.sync.aligned.m16n8k16.row.col.f32.bf16.bf16.f32 "
        "{%0,%1,%2,%3}, {%4,%5,%6,%7}, {%8,%9}, {%0,%1,%2,%3};"
        : "+f"(c[0]), "+f"(c[1]), "+f"(c[2]), "+f"(c[3])
        : "r"(a[0]), "r"(a[1]), "r"(a[2]), "r"(a[3]), "r"(b[0]), "r"(b[1]));
}
__device__ __forceinline__ __nv_bfloat162 split2(float2 x, __nv_bfloat162* lo) {
    __nv_bfloat16 hx = __float2bfloat16(x.x), hy = __float2bfloat16(x.y);
    lo->x = __float2bfloat16(x.x - __bfloat162float(hx));
    lo->y = __float2bfloat16(x.y - __bfloat162float(hy));
    __nv_bfloat162 h; h.x = hx; h.y = hy; return h;
}

// ---------------------------------------------------------------------------
// Pass A: e = exp((q/8)·k^T), causal+padding masked -> attn (unnormalized),
// row sums -> g_l. 256 thr, warp grid 4m x 2n, warp tile 32x64, HMMA bf16 split.
// ---------------------------------------------------------------------------
#define A_QH 0
#define A_QL 18432
#define A_KH 36864
#define A_KL 55296
#define A_MSK 73728
#define A_LP  74240
#define A_SZ  75264

__global__ void __launch_bounds__(256, 2)
scores_mma(const float* __restrict__ q, const float* __restrict__ k,
           const int* __restrict__ mask, float* __restrict__ attn)
{
    extern __shared__ char smem[];
    const int qt = (NT - 1) - blockIdx.x;   // heavy tiles first
    const int bh = blockIdx.y, b = bh >> 4;
    const int tid = threadIdx.x, wid = tid >> 5, lane = tid & 31;
    const int g = lane >> 2, t2 = (lane & 3) << 1;

    __nv_bfloat16* qh = (__nv_bfloat16*)(smem + A_QH);
    __nv_bfloat16* ql = (__nv_bfloat16*)(smem + A_QL);
    __nv_bfloat16* kh = (__nv_bfloat16*)(smem + A_KH);
    __nv_bfloat16* kl = (__nv_bfloat16*)(smem + A_KL);
    int*   msk = (int*)(smem + A_MSK);
    float* lp  = (float*)(smem + A_LP);
    const uint32_t sb = smem_u32(smem);
    const uint32_t aQH = sb + A_QH, aQL = sb + A_QL, aKH = sb + A_KH, aKL = sb + A_KL;

    // stage Q hi/lo (pre-scaled by 1/8), stride 72 bf16 rows
    const float* qbase = q + ((size_t)bh * SEQ + (size_t)qt * TILE) * HDIM;
    for (int i = tid; i < TILE * HDIM / 2; i += 256) {
        int r = i >> 5, c2 = (i & 31) << 1;
        float2 x = *(const float2*)&qbase[r * HDIM + c2];
        x.x *= 0.125f; x.y *= 0.125f;
        __nv_bfloat162 lo, hi = split2(x, &lo);
        *(__nv_bfloat162*)&qh[r * 72 + c2] = hi;
        *(__nv_bfloat162*)&ql[r * 72 + c2] = lo;
    }

    const int m0w = (wid >> 1) * 32, n0w = (wid & 1) * 64;
    const int arow = (lane & 7) + ((lane >> 3) & 1) * 8;  // + mt*16 + m0w
    const int acol = ((lane >> 4) & 1) * 8;               // + ks*16
    const int brow = lane & 7;                            // + n0
    const int bcol = ((lane >> 3) & 1) * 8;               // + ks*16

    float* attnrow = attn + (size_t)bh * SEQ * SEQ + (size_t)qt * TILE * SEQ;
    const int* mrow = mask + b * SEQ;

    float rs[2][2] = {{0.f, 0.f}, {0.f, 0.f}};

    for (int kt = 0; kt <= qt; ++kt) {
        __syncthreads();    // Q staged / prior iter's smem reads done
        const float* kbase = k + ((size_t)bh * SEQ + (size_t)kt * TILE) * HDIM;
        for (int i = tid; i < TILE * HDIM / 2; i += 256) {
            int r = i >> 5, c2 = (i & 31) << 1;
            float2 x = *(const float2*)&kbase[r * HDIM + c2];
            __nv_bfloat162 lo, hi = split2(x, &lo);
            *(__nv_bfloat162*)&kh[r * 72 + c2] = hi;
            *(__nv_bfloat162*)&kl[r * 72 + c2] = lo;
        }
        if (tid < 128) msk[tid] = mrow[kt * TILE + tid];
        __syncthreads();

        float acc[2][8][4];
        #pragma unroll
        for (int mt = 0; mt < 2; mt++)
            #pragma unroll
            for (int nt = 0; nt < 8; nt++)
                #pragma unroll
                for (int j = 0; j < 4; j++) acc[mt][nt][j] = 0.f;

        #pragma unroll
        for (int ks = 0; ks < 4; ks++) {
            uint32_t a0h[4], a1h[4], a0l[4], a1l[4];
            uint32_t ao0 = (uint32_t)(((m0w + arow) * 72 + ks * 16 + acol) * 2);
            uint32_t ao1 = ao0 + 16 * 72 * 2;
            ldsm_x4(a0h, aQH + ao0); ldsm_x4(a1h, aQH + ao1);
            ldsm_x4(a0l, aQL + ao0); ldsm_x4(a1l, aQL + ao1);
            #pragma unroll
            for (int nt = 0; nt < 8; nt++) {
                uint32_t bhf[2], blf[2];
                uint32_t bo = (uint32_t)(((n0w + nt * 8 + brow) * 72 + ks * 16 + bcol) * 2);
                ldsm_x2(bhf, aKH + bo);
                ldsm_x2(blf, aKL + bo);
                mma16816(acc[0][nt], a0h, bhf);
                mma16816(acc[1][nt], a1h, bhf);
                mma16816(acc[0][nt], a0l, bhf);
                mma16816(acc[1][nt], a1l, bhf);
                mma16816(acc[0][nt], a0h, blf);
                mma16816(acc[1][nt], a1h, blf);
            }
        }

        // epilogue: mask, exp, store e, accumulate row sums
        #pragma unroll
        for (int mt = 0; mt < 2; mt++) {
            const int rl = m0w + mt * 16 + g;
            const int ra = qt * TILE + rl, rb = ra + 8;
            float* rowa = attnrow + (size_t)rl * SEQ + kt * TILE;
            float* rowb = rowa + (size_t)8 * SEQ;
            #pragma unroll
            for (int nt = 0; nt < 8; nt++) {
                int lc = n0w + nt * 8 + t2;
                int gc = kt * TILE + lc;
                bool k0 = msk[lc] != 0, k1 = msk[lc + 1] != 0;
                float e0 = (k0 && gc     <= ra) ? __expf(acc[mt][nt][0]) : 0.f;
                float e1 = (k1 && gc + 1 <= ra) ? __expf(acc[mt][nt][1]) : 0.f;
                float e2 = (k0 && gc     <= rb) ? __expf(acc[mt][nt][2]) : 0.f;
                float e3 = (k1 && gc + 1 <= rb) ? __expf(acc[mt][nt][3]) : 0.f;
                rs[mt][0] += e0 + e1;
                rs[mt][1] += e2 + e3;
                *(float2*)(rowa + lc) = make_float2(e0, e1);
                *(float2*)(rowb + lc) = make_float2(e2, e3);
            }
        }
    }

    // quad-reduce row sums, combine the two n-warps via smem
    #pragma unroll
    for (int mt = 0; mt < 2; mt++)
        #pragma unroll
        for (int h = 0; h < 2; h++) {
            rs[mt][h] += __shfl_xor_sync(0xFFFFFFFFu, rs[mt][h], 1);
            rs[mt][h] += __shfl_xor_sync(0xFFFFFFFFu, rs[mt][h], 2);
        }
    __syncthreads();
    if ((lane & 3) == 0) {
        int nw = wid & 1;
        lp[nw * 128 + m0w + g]          = rs[0][0];
        lp[nw * 128 + m0w + g + 8]      = rs[0][1];
        lp[nw * 128 + m0w + 16 + g]     = rs[1][0];
        lp[nw * 128 + m0w + 16 + g + 8] = rs[1][1];
    }
    __syncthreads();
    if (tid < 128)
        g_l[bh * SEQ + qt * TILE + tid] = lp[tid] + lp[128 + tid];
}

// ---------------------------------------------------------------------------
// Pass B: p = e/l (rewritten in attn), out = p @ v via HMMA, zero upper tiles.
// 256 thr, warp grid 4m x 2n, warp tile 32x32. V staged natural [k][n],
// B fragments via ldmatrix.trans.
// ---------------------------------------------------------------------------
#define B_PH   0
#define B_PL   34816
#define B_VH   69632
#define B_VL   88064
#define B_INVL 106496
#define B_SZ   107008

__global__ void __launch_bounds__(256, 2)
av_mma(const float* __restrict__ v, float* __restrict__ attn, float* __restrict__ out)
{
    extern __shared__ char smem[];
    const int qt = (NT - 1) - blockIdx.x;
    const int bh = blockIdx.y;
    const int tid = threadIdx.x, wid = tid >> 5, lane = tid & 31;
    const int g = lane >> 2, t2 = (lane & 3) << 1;

    __nv_bfloat16* ph = (__nv_bfloat16*)(smem + B_PH);
    __nv_bfloat16* pl = (__nv_bfloat16*)(smem + B_PL);
    __nv_bfloat16* vh = (__nv_bfloat16*)(smem + B_VH);
    __nv_bfloat16* vl = (__nv_bfloat16*)(smem + B_VL);
    float* invl = (float*)(smem + B_INVL);
    const uint32_t sb = smem_u32(smem);
    const uint32_t aPH = sb + B_PH, aPL = sb + B_PL, aVH = sb + B_VH, aVL = sb + B_VL;

    if (tid < 128) invl[tid] = 1.0f / g_l[bh * SEQ + qt * TILE + tid];

    float* attnrow = attn + (size_t)bh * SEQ * SEQ + (size_t)qt * TILE * SEQ;
    const int m0w = (wid >> 1) * 32, n0w = (wid & 1) * 32;
    const int arow = (lane & 7) + ((lane >> 3) & 1) * 8;
    const int acol = ((lane >> 4) & 1) * 8;
    const int vrow = lane & 15;   // k-row within 16-step (x2.trans uses lanes 0-15)

    float acc[2][4][4];
    #pragma unroll
    for (int mt = 0; mt < 2; mt++)
        #pragma unroll
        for (int nt = 0; nt < 4; nt++)
            #pragma unroll
            for (int j = 0; j < 4; j++) acc[mt][nt][j] = 0.f;

    for (int kt = 0; kt <= qt; ++kt) {
        __syncthreads();   // invl ready / prior MMA smem reads done

        // stage P: read e, normalize, write p back, split hi/lo (stride 136)
        for (int i = tid; i < TILE * TILE / 4; i += 256) {
            int r = i >> 5, c0 = (i & 31) << 2;
            size_t gi = (size_t)r * SEQ + kt * TILE + c0;
            float4 e = *(float4*)&attnrow[gi];
            float il = invl[r];
            e.x *= il; e.y *= il; e.z *= il; e.w *= il;
            *(float4*)&attnrow[gi] = e;
            __nv_bfloat162 lo0, hi0 = split2(make_float2(e.x, e.y), &lo0);
            __nv_bfloat162 lo1, hi1 = split2(make_float2(e.z, e.w), &lo1);
            *(__nv_bfloat162*)&ph[r * 136 + c0]     = hi0;
            *(__nv_bfloat162*)&ph[r * 136 + c0 + 2] = hi1;
            *(__nv_bfloat162*)&pl[r * 136 + c0]     = lo0;
            *(__nv_bfloat162*)&pl[r * 136 + c0 + 2] = lo1;
        }
        // stage V natural [k][n] hi/lo (stride 72)
        const float* vbase = v + ((size_t)bh * SEQ + (size_t)kt * TILE) * HDIM;
        for (int i = tid; i < TILE * HDIM / 2; i += 256) {
            int r = i >> 5, c2 = (i & 31) << 1;
            float2 x = *(const float2*)&vbase[r * HDIM + c2];
            __nv_bfloat162 lo, hi = split2(x, &lo);
            *(__nv_bfloat162*)&vh[r * 72 + c2] = hi;
            *(__nv_bfloat162*)&vl[r * 72 + c2] = lo;
        }
        __syncthreads();

        #pragma unroll
        for (int ks = 0; ks < 8; ks++) {
            uint32_t a0h[4], a1h[4], a0l[4], a1l[4];
            uint32_t ao0 = (uint32_t)(((m0w + arow) * 136 + ks * 16 + acol) * 2);
            uint32_t ao1 = ao0 + 16 * 136 * 2;
            ldsm_x4(a0h, aPH + ao0); ldsm_x4(a1h, aPH + ao1);
            ldsm_x4(a0l, aPL + ao0); ldsm_x4(a1l, aPL + ao1);
            #pragma unroll
            for (int nt = 0; nt < 4; nt++) {
                uint32_t bhf[2], blf[2];
                uint32_t bo = (uint32_t)(((ks * 16 + vrow) * 72 + n0w + nt * 8) * 2);
                ldsm_x2t(bhf, aVH + bo);
                ldsm_x2t(blf, aVL + bo);
                mma16816(acc[0][nt], a0h, bhf);
                mma16816(acc[1][nt], a1h, bhf);
                mma16816(acc[0][nt], a0l, bhf);
                mma16816(acc[1][nt], a1l, bhf);
                mma16816(acc[0][nt], a0h, blf);
                mma16816(acc[1][nt], a1h, blf);
            }
        }
    }

    // write out tile
    float* obase = out + ((size_t)bh * SEQ + (size_t)qt * TILE) * HDIM;
    #pragma unroll
    for (int mt = 0; mt < 2; mt++) {
        int rl = m0w + mt * 16 + g;
        #pragma unroll
        for (int nt = 0; nt < 4; nt++) {
            int c = n0w + nt * 8 + t2;
            *(float2*)&obase[(size_t)rl * HDIM + c] =
                make_float2(acc[mt][nt][0], acc[mt][nt][1]);
            *(float2*)&obase[(size_t)(rl + 8) * HDIM + c] =
                make_float2(acc[mt][nt][2], acc[mt][nt][3]);
        }
    }

    // zero strictly-upper tiles of this block row
    const int cols = SEQ - (qt + 1) * TILE;
    if (cols > 0) {
        float* up = attnrow + (qt + 1) * TILE;
        const float4 z = make_float4(0.f, 0.f, 0.f, 0.f);
        for (int r = wid; r < TILE; r += 8)
            for (int c = lane * 4; c < cols; c += 128)
                *(float4*)&up[(size_t)r * SEQ + c] = z;
    }
}

// ---------------------------------------------------------------------------
extern "C" void kernel_launch(void* const* d_in, const int* in_sizes, int n_in,
                              void* d_out, int out_size)
{
    const float* q    = (const float*)d_in[0];
    const float* k    = (const float*)d_in[1];
    const float* v    = (const float*)d_in[2];
    const int*   mask = (const int*)d_in[3];

    float* out  = (float*)d_out;                       // [B,H,S,D]
    float* attn = out + (size_t)BH * SEQ * HDIM;       // [B,H,S,S]

    cudaFuncSetAttribute(scores_mma, cudaFuncAttributeMaxDynamicSharedMemorySize, A_SZ);
    cudaFuncSetAttribute(av_mma,     cudaFuncAttributeMaxDynamicSharedMemorySize, B_SZ);

    dim3 grid(NT, BH);
    scores_mma<<<grid, 256, A_SZ>>>(q, k, mask, attn);
    av_mma<<<grid, 256, B_SZ>>>(v, attn, out);
}

// round 4
// speedup vs baseline: 1.6201x; 1.1193x over previous
#include <cuda_runtime.h>
#include <cuda_bf16.h>
#include <cstdint>

// B=2,H=16,S=2048,D=64 fp32 causal attention; d_out = out[B,H,S,D] ++ attn[B,H,S,S]
#define SEQ   2048
#define HDIM  64
#define BH    32
#define TILE  128
#define NT    (SEQ / TILE)   // 16

// smem layout (bytes)
#define S_QH   0
#define S_QL   18432
#define S_KH   36864
#define S_KL   55296
#define S_VH   73728
#define S_VL   92160
#define S_MSK  110592
#define S_INV  111104
#define S_SZ   111616

// ---------------------------------------------------------------------------
__device__ __forceinline__ uint32_t smem_u32(const void* p) {
    uint32_t a;
    asm("{ .reg .u64 t; cvta.to.shared.u64 t, %1; cvt.u32.u64 %0, t; }" : "=r"(a) : "l"(p));
    return a;
}
__device__ __forceinline__ void ldsm_x4(uint32_t* r, uint32_t a) {
    asm volatile("ldmatrix.sync.aligned.m8n8.x4.shared.b16 {%0,%1,%2,%3}, [%4];"
        : "=r"(r[0]), "=r"(r[1]), "=r"(r[2]), "=r"(r[3]) : "r"(a));
}
__device__ __forceinline__ void ldsm_x2(uint32_t* r, uint32_t a) {
    asm volatile("ldmatrix.sync.aligned.m8n8.x2.shared.b16 {%0,%1}, [%2];"
        : "=r"(r[0]), "=r"(r[1]) : "r"(a));
}
__device__ __forceinline__ void ldsm_x2t(uint32_t* r, uint32_t a) {
    asm volatile("ldmatrix.sync.aligned.m8n8.x2.trans.shared.b16 {%0,%1}, [%2];"
        : "=r"(r[0]), "=r"(r[1]) : "r"(a));
}
__device__ __forceinline__ void mma16816(float* c, const uint32_t* a, const uint32_t* b) {
    asm volatile("mma.sync.aligned.m16n8k16.row.col.f32.bf16.bf16.f32 "
        "{%0,%1,%2,%3}, {%4,%5,%6,%7}, {%8,%9}, {%0,%1,%2,%3};"
        : "+f"(c[0]), "+f"(c[1]), "+f"(c[2]), "+f"(c[3])
        : "r"(a[0]), "r"(a[1]), "r"(a[2]), "r"(a[3]), "r"(b[0]), "r"(b[1]));
}
__device__ __forceinline__ __nv_bfloat162 split2(float2 x, __nv_bfloat162* lo) {
    __nv_bfloat16 hx = __float2bfloat16(x.x), hy = __float2bfloat16(x.y);
    lo->x = __float2bfloat16(x.x - __bfloat162float(hx));
    lo->y = __float2bfloat16(x.y - __bfloat162float(hy));
    __nv_bfloat162 h; h.x = hx; h.y = hy; return h;
}
__device__ __forceinline__ void pack_split(float x, float y, uint32_t& h, uint32_t& l) {
    __nv_bfloat162 hv, lv;
    hv = split2(make_float2(x, y), &lv);
    h = *reinterpret_cast<uint32_t*>(&hv);
    l = *reinterpret_cast<uint32_t*>(&lv);
}

// ---------------------------------------------------------------------------
// One fused kernel per (qt, bh) tile. 256 threads = 8 warps, warp tile 16x128.
// ---------------------------------------------------------------------------
__global__ void __launch_bounds__(256, 2)
fused_attn(const float* __restrict__ q, const float* __restrict__ k,
           const float* __restrict__ v, const int* __restrict__ mask,
           float* __restrict__ out, float* __restrict__ attn)
{
    extern __shared__ char smem[];
    const int qt  = (NT - 1) - blockIdx.x;   // heavy tiles first
    const int bh  = blockIdx.y, b = bh >> 4;
    const int tid = threadIdx.x, wid = tid >> 5, lane = tid & 31;
    const int g = lane >> 2, t2 = (lane & 3) << 1;
    const int m0w = wid * 16;

    __nv_bfloat16* qh = (__nv_bfloat16*)(smem + S_QH);
    __nv_bfloat16* ql = (__nv_bfloat16*)(smem + S_QL);
    __nv_bfloat16* kh = (__nv_bfloat16*)(smem + S_KH);
    __nv_bfloat16* kl = (__nv_bfloat16*)(smem + S_KL);
    __nv_bfloat16* vh = (__nv_bfloat16*)(smem + S_VH);
    __nv_bfloat16* vl = (__nv_bfloat16*)(smem + S_VL);
    int*   msk  = (int*)(smem + S_MSK);
    float* invl = (float*)(smem + S_INV);
    const uint32_t sb = smem_u32(smem);

    // ldmatrix source addresses (byte offsets within smem)
    const uint32_t qaddr = sb + S_QH + (uint32_t)(((m0w + (lane & 15)) * 72 + ((lane >> 4) & 1) * 8) * 2);
    const uint32_t kaddr = sb + S_KH + (uint32_t)(((lane & 7) * 72 + ((lane >> 3) & 1) * 8) * 2);
    const uint32_t vaddr = sb + S_VH + (uint32_t)(((lane & 15) * 72) * 2);

    // stage Q (pre-scaled by 1/8) hi/lo, stride 72 bf16
    const float* qbase = q + ((size_t)bh * SEQ + (size_t)qt * TILE) * HDIM;
    for (int i = tid; i < TILE * HDIM / 2; i += 256) {
        int r = i >> 5, c2 = (i & 31) << 1;
        float2 x = *(const float2*)&qbase[r * HDIM + c2];
        x.x *= 0.125f; x.y *= 0.125f;
        __nv_bfloat162 lo, hi = split2(x, &lo);
        *(__nv_bfloat162*)&qh[r * 72 + c2] = hi;
        *(__nv_bfloat162*)&ql[r * 72 + c2] = lo;
    }

    float* attnrow = attn + (size_t)bh * SEQ * SEQ + (size_t)qt * TILE * SEQ;
    const int* mrow = mask + b * SEQ;

    float acc_o[8][4];
    #pragma unroll
    for (int nt = 0; nt < 8; nt++)
        #pragma unroll
        for (int j = 0; j < 4; j++) acc_o[nt][j] = 0.f;
    float rs0 = 0.f, rs1 = 0.f;

    for (int kt = 0; kt <= qt; ++kt) {
        __syncthreads();   // previous iter's smem reads done (and Q staged, 1st iter)
        const float* kbase = k + ((size_t)bh * SEQ + (size_t)kt * TILE) * HDIM;
        const float* vbase = v + ((size_t)bh * SEQ + (size_t)kt * TILE) * HDIM;
        for (int i = tid; i < TILE * HDIM / 2; i += 256) {
            int r = i >> 5, c2 = (i & 31) << 1;
            float2 xk = *(const float2*)&kbase[r * HDIM + c2];
            float2 xv = *(const float2*)&vbase[r * HDIM + c2];
            __nv_bfloat162 lok, hik = split2(xk, &lok);
            __nv_bfloat162 lov, hiv = split2(xv, &lov);
            *(__nv_bfloat162*)&kh[r * 72 + c2] = hik;
            *(__nv_bfloat162*)&kl[r * 72 + c2] = lok;
            *(__nv_bfloat162*)&vh[r * 72 + c2] = hiv;
            *(__nv_bfloat162*)&vl[r * 72 + c2] = lov;
        }
        if (tid < 128) msk[tid] = mrow[kt * TILE + tid];
        __syncthreads();

        // ---- QK^T: S tile 16x128 per warp, 3-term bf16 split ----
        float acc[16][4];
        #pragma unroll
        for (int nt = 0; nt < 16; nt++)
            #pragma unroll
            for (int j = 0; j < 4; j++) acc[nt][j] = 0.f;

        #pragma unroll
        for (int ks = 0; ks < 4; ks++) {
            uint32_t ah_[4], al_[4];
            ldsm_x4(ah_, qaddr + ks * 32);
            ldsm_x4(al_, qaddr + 18432 + ks * 32);
            #pragma unroll
            for (int nt = 0; nt < 16; nt++) {
                uint32_t bh_[2], bl_[2];
                uint32_t ka = kaddr + (uint32_t)(nt * 8 * 72 * 2) + ks * 32;
                ldsm_x2(bh_, ka);
                ldsm_x2(bl_, ka + 18432);
                mma16816(acc[nt], ah_, bh_);
                mma16816(acc[nt], al_, bh_);
                mma16816(acc[nt], ah_, bl_);
            }
        }

        // ---- mask + exp + store e + rowsums ----
        const bool diag = (kt == qt);
        const int ra = qt * TILE + m0w + g, rb = ra + 8;
        float* rowa = attnrow + (size_t)(m0w + g) * SEQ + kt * TILE;
        float* rowb = rowa + (size_t)8 * SEQ;
        #pragma unroll
        for (int nt = 0; nt < 16; nt++) {
            int lc = nt * 8 + t2, gc = kt * TILE + lc;
            bool k0 = msk[lc] != 0, k1 = msk[lc + 1] != 0;
            float e0 = (k0 && (!diag || gc     <= ra)) ? __expf(acc[nt][0]) : 0.f;
            float e1 = (k1 && (!diag || gc + 1 <= ra)) ? __expf(acc[nt][1]) : 0.f;
            float e2 = (k0 && (!diag || gc     <= rb)) ? __expf(acc[nt][2]) : 0.f;
            float e3 = (k1 && (!diag || gc + 1 <= rb)) ? __expf(acc[nt][3]) : 0.f;
            rs0 += e0 + e1; rs1 += e2 + e3;
            acc[nt][0] = e0; acc[nt][1] = e1; acc[nt][2] = e2; acc[nt][3] = e3;
            *(float2*)(rowa + lc) = make_float2(e0, e1);
            *(float2*)(rowb + lc) = make_float2(e2, e3);
        }

        // ---- P·V: repack e-frags (C-layout -> A-layout) and accumulate ----
        #pragma unroll
        for (int ks = 0; ks < 8; ks++) {
            uint32_t eh[4], el[4];
            pack_split(acc[2*ks][0],     acc[2*ks][1],     eh[0], el[0]);
            pack_split(acc[2*ks][2],     acc[2*ks][3],     eh[1], el[1]);
            pack_split(acc[2*ks + 1][0], acc[2*ks + 1][1], eh[2], el[2]);
            pack_split(acc[2*ks + 1][2], acc[2*ks + 1][3], eh[3], el[3]);
            #pragma unroll
            for (int nt = 0; nt < 8; nt++) {
                uint32_t vhf[2], vlf[2];
                uint32_t va = vaddr + (uint32_t)(ks * 16 * 72 * 2) + nt * 16;
                ldsm_x2t(vhf, va);
                ldsm_x2t(vlf, va + 18432);
                mma16816(acc_o[nt], eh, vhf);
                mma16816(acc_o[nt], el, vhf);
                mma16816(acc_o[nt], eh, vlf);
            }
        }
    }

    // ---- rowsum reduce -> invl ----
    rs0 += __shfl_xor_sync(0xFFFFFFFFu, rs0, 1);
    rs0 += __shfl_xor_sync(0xFFFFFFFFu, rs0, 2);
    rs1 += __shfl_xor_sync(0xFFFFFFFFu, rs1, 1);
    rs1 += __shfl_xor_sync(0xFFFFFFFFu, rs1, 2);
    if ((lane & 3) == 0) {
        invl[m0w + g]     = 1.0f / rs0;
        invl[m0w + g + 8] = 1.0f / rs1;
    }
    __syncthreads();

    // ---- write out = acc_o * invl ----
    float* obase = out + ((size_t)bh * SEQ + (size_t)qt * TILE) * HDIM;
    const float il0 = invl[m0w + g], il1 = invl[m0w + g + 8];
    #pragma unroll
    for (int nt = 0; nt < 8; nt++) {
        int c = nt * 8 + t2;
        *(float2*)&obase[(size_t)(m0w + g) * HDIM + c] =
            make_float2(acc_o[nt][0] * il0, acc_o[nt][1] * il0);
        *(float2*)&obase[(size_t)(m0w + g + 8) * HDIM + c] =
            make_float2(acc_o[nt][2] * il1, acc_o[nt][3] * il1);
    }

    // ---- streaming phase: p = e * invl in place, zero upper triangle ----
    const int lim4 = (qt + 1) * TILE / 4;   // float4s per row that hold e
    for (int i = tid; i < TILE * (SEQ / 4); i += 256) {
        int r = i >> 9, c4 = i & 511;
        float4* pp = (float4*)&attnrow[(size_t)r * SEQ] + c4;
        if (c4 < lim4) {
            float4 e = *pp;
            float il = invl[r];
            e.x *= il; e.y *= il; e.z *= il; e.w *= il;
            *pp = e;
        } else {
            *pp = make_float4(0.f, 0.f, 0.f, 0.f);
        }
    }
}

// ---------------------------------------------------------------------------
extern "C" void kernel_launch(void* const* d_in, const int* in_sizes, int n_in,
                              void* d_out, int out_size)
{
    const float* q    = (const float*)d_in[0];
    const float* k    = (const float*)d_in[1];
    const float* v    = (const float*)d_in[2];
    const int*   mask = (const int*)d_in[3];

    float* out  = (float*)d_out;                       // [B,H,S,D]
    float* attn = out + (size_t)BH * SEQ * HDIM;       // [B,H,S,S]

    cudaFuncSetAttribute(fused_attn, cudaFuncAttributeMaxDynamicSharedMemorySize, S_SZ);

    dim3 grid(NT, BH);
    fused_attn<<<grid, 256, S_SZ>>>(q, k, v, mask, out, attn);
}

// round 5
// speedup vs baseline: 1.8036x; 1.1133x over previous
#include <cuda_runtime.h>
#include <cuda_bf16.h>
#include <cstdint>

// B=2,H=16,S=2048,D=64 fp32 causal attention; d_out = out[B,H,S,D] ++ attn[B,H,S,S]
#define SEQ   2048
#define HDIM  64
#define BH    32
#define TILE  128               // q-tile rows per CTA
#define TK    64                // kv-tile rows per pipeline step
#define NT    (SEQ / TILE)      // 16

// smem layout (bytes)
#define S_QH   0                // 128*72*2 = 18432
#define S_QL   18432
#define S_KH   36864            // 64*72*2 = 9216
#define S_KL   46080
#define S_VH   55296
#define S_VL   64512
#define S_RAWK 73728            // 64*64*4 = 16384
#define S_RAWV 90112
#define S_MSK  106496           // 2 x 256 (double buffered)
#define S_INV  107008           // 128 floats
#define S_SZ   107520

// ---------------------------------------------------------------------------
__device__ __forceinline__ uint32_t smem_u32(const void* p) {
    uint32_t a;
    asm("{ .reg .u64 t; cvta.to.shared.u64 t, %1; cvt.u32.u64 %0, t; }" : "=r"(a) : "l"(p));
    return a;
}
__device__ __forceinline__ void ldsm_x4(uint32_t* r, uint32_t a) {
    asm volatile("ldmatrix.sync.aligned.m8n8.x4.shared.b16 {%0,%1,%2,%3}, [%4];"
        : "=r"(r[0]), "=r"(r[1]), "=r"(r[2]), "=r"(r[3]) : "r"(a));
}
__device__ __forceinline__ void ldsm_x4t(uint32_t* r, uint32_t a) {
    asm volatile("ldmatrix.sync.aligned.m8n8.x4.trans.shared.b16 {%0,%1,%2,%3}, [%4];"
        : "=r"(r[0]), "=r"(r[1]), "=r"(r[2]), "=r"(r[3]) : "r"(a));
}
__device__ __forceinline__ void mma16816(float* c, const uint32_t* a, const uint32_t* b) {
    asm volatile("mma.sync.aligned.m16n8k16.row.col.f32.bf16.bf16.f32 "
        "{%0,%1,%2,%3}, {%4,%5,%6,%7}, {%8,%9}, {%0,%1,%2,%3};"
        : "+f"(c[0]), "+f"(c[1]), "+f"(c[2]), "+f"(c[3])
        : "r"(a[0]), "r"(a[1]), "r"(a[2]), "r"(a[3]), "r"(b[0]), "r"(b[1]));
}
__device__ __forceinline__ void cp16(uint32_t s, const void* g) {
    asm volatile("cp.async.cg.shared.global [%0], [%1], 16;" :: "r"(s), "l"(g));
}
#define CP_COMMIT() asm volatile("cp.async.commit_group;" ::: "memory")
#define CP_WAIT0()  asm volatile("cp.async.wait_group 0;" ::: "memory")

__device__ __forceinline__ __nv_bfloat162 split2(float2 x, __nv_bfloat162* lo) {
    __nv_bfloat16 hx = __float2bfloat16(x.x), hy = __float2bfloat16(x.y);
    lo->x = __float2bfloat16(x.x - __bfloat162float(hx));
    lo->y = __float2bfloat16(x.y - __bfloat162float(hy));
    __nv_bfloat162 h; h.x = hx; h.y = hy; return h;
}
__device__ __forceinline__ void pack_split(float x, float y, uint32_t& h, uint32_t& l) {
    __nv_bfloat162 hv, lv;
    hv = split2(make_float2(x, y), &lv);
    h = *reinterpret_cast<uint32_t*>(&hv);
    l = *reinterpret_cast<uint32_t*>(&lv);
}
__device__ __forceinline__ uint32_t u32of(__nv_bfloat162 v) {
    return *reinterpret_cast<uint32_t*>(&v);
}

// ---------------------------------------------------------------------------
// Fused causal attention, cp.async-pipelined. 256 thr = 8 warps, warp 16x64.
// ---------------------------------------------------------------------------
__global__ void __launch_bounds__(256, 2)
fused_attn(const float* __restrict__ q, const float* __restrict__ k,
           const float* __restrict__ v, const int* __restrict__ mask,
           float* __restrict__ out, float* __restrict__ attn)
{
    extern __shared__ char smem[];
    const int qt  = (NT - 1) - blockIdx.x;   // heavy tiles first
    const int bh  = blockIdx.y, b = bh >> 4;
    const int tid = threadIdx.x, wid = tid >> 5, lane = tid & 31;
    const int g = lane >> 2, t2 = (lane & 3) << 1;
    const int m0w = wid * 16;

    __nv_bfloat16* qh = (__nv_bfloat16*)(smem + S_QH);
    __nv_bfloat16* ql = (__nv_bfloat16*)(smem + S_QL);
    __nv_bfloat16* kh = (__nv_bfloat16*)(smem + S_KH);
    __nv_bfloat16* kl = (__nv_bfloat16*)(smem + S_KL);
    __nv_bfloat16* vh = (__nv_bfloat16*)(smem + S_VH);
    __nv_bfloat16* vl = (__nv_bfloat16*)(smem + S_VL);
    float* invl = (float*)(smem + S_INV);
    const uint32_t sb = smem_u32(smem);

    // ldmatrix source addresses
    const uint32_t qaddr = sb + S_QH +
        (uint32_t)(((m0w + (lane & 15)) * 72 + ((lane >> 4) & 1) * 8) * 2);
    const uint32_t kaddr = sb + S_KH +
        (uint32_t)((((lane & 7) + ((lane >> 4) & 1) * 8) * 72 + ((lane >> 3) & 1) * 8) * 2);
    const uint32_t vaddr = sb + S_VH +
        (uint32_t)(((lane & 15) * 72 + ((lane >> 4) & 1) * 8) * 2);

    // stage Q (pre-scaled by 1/8) hi/lo, row stride 72 bf16
    const float* qbase = q + ((size_t)bh * SEQ + (size_t)qt * TILE) * HDIM;
    for (int i = tid; i < TILE * HDIM / 2; i += 256) {
        int r = i >> 5, c2 = (i & 31) << 1;
        float2 x = *(const float2*)&qbase[r * HDIM + c2];
        x.x *= 0.125f; x.y *= 0.125f;
        __nv_bfloat162 lo, hi = split2(x, &lo);
        *(__nv_bfloat162*)&qh[r * 72 + c2] = hi;
        *(__nv_bfloat162*)&ql[r * 72 + c2] = lo;
    }

    float* attnrow = attn + (size_t)bh * SEQ * SEQ + (size_t)qt * TILE * SEQ;
    const int* mrow = mask + b * SEQ;
    const float* kbh = k + (size_t)bh * SEQ * HDIM;
    const float* vbh = v + (size_t)bh * SEQ * HDIM;

    float acc_o[8][4];
    #pragma unroll
    for (int nt = 0; nt < 8; nt++)
        #pragma unroll
        for (int j = 0; j < 4; j++) acc_o[nt][j] = 0.f;
    float rs0 = 0.f, rs1 = 0.f;

    const int nkt = 2 * qt + 2;   // number of 64-row kv tiles

    // issue cp.async for tile 0
    {
        const char* kg = (const char*)(kbh + (size_t)0 * TK * HDIM);
        const char* vg = (const char*)(vbh + (size_t)0 * TK * HDIM);
        #pragma unroll
        for (int t = 0; t < 4; t++) {
            int idx = tid + t * 256;
            cp16(sb + S_RAWK + idx * 16, kg + idx * 16);
            cp16(sb + S_RAWV + idx * 16, vg + idx * 16);
        }
        if (tid < 16) cp16(sb + S_MSK + tid * 16, mrow + tid * 4);
        CP_COMMIT();
    }

    for (int j = 0; j < nkt; ++j) {
        CP_WAIT0();
        __syncthreads();    // raw tile ready everywhere; prior MMA reads done

        // convert raw fp32 -> bf16 hi/lo split buffers
        {
            const float4* rk = (const float4*)(smem + S_RAWK);
            const float4* rv = (const float4*)(smem + S_RAWV);
            #pragma unroll
            for (int t = 0; t < 4; t++) {
                int idx = tid + t * 256;            // 0..1023
                int r = idx >> 4, c4 = (idx & 15) << 2;
                float4 xk = rk[idx];
                float4 xv = rv[idx];
                __nv_bfloat162 kl0, kh0 = split2(make_float2(xk.x, xk.y), &kl0);
                __nv_bfloat162 kl1, kh1 = split2(make_float2(xk.z, xk.w), &kl1);
                __nv_bfloat162 vl0, vh0 = split2(make_float2(xv.x, xv.y), &vl0);
                __nv_bfloat162 vl1, vh1 = split2(make_float2(xv.z, xv.w), &vl1);
                *(uint2*)&kh[r * 72 + c4] = make_uint2(u32of(kh0), u32of(kh1));
                *(uint2*)&kl[r * 72 + c4] = make_uint2(u32of(kl0), u32of(kl1));
                *(uint2*)&vh[r * 72 + c4] = make_uint2(u32of(vh0), u32of(vh1));
                *(uint2*)&vl[r * 72 + c4] = make_uint2(u32of(vl0), u32of(vl1));
            }
        }
        __syncthreads();    // split buffers ready; raw buffer free

        // prefetch next tile (streams during MMA below)
        if (j + 1 < nkt) {
            const char* kg = (const char*)(kbh + (size_t)(j + 1) * TK * HDIM);
            const char* vg = (const char*)(vbh + (size_t)(j + 1) * TK * HDIM);
            #pragma unroll
            for (int t = 0; t < 4; t++) {
                int idx = tid + t * 256;
                cp16(sb + S_RAWK + idx * 16, kg + idx * 16);
                cp16(sb + S_RAWV + idx * 16, vg + idx * 16);
            }
            if (tid < 16)
                cp16(sb + S_MSK + ((j + 1) & 1) * 256 + tid * 16,
                     mrow + (j + 1) * TK + tid * 4);
        }
        CP_COMMIT();   // commit (possibly empty) group so wait_group 0 is well-defined

        // ---- QK^T: S tile 16x64 per warp, 3-term bf16 split ----
        float acc[8][4];
        #pragma unroll
        for (int nt = 0; nt < 8; nt++)
            #pragma unroll
            for (int jj = 0; jj < 4; jj++) acc[nt][jj] = 0.f;

        #pragma unroll
        for (int ks = 0; ks < 4; ks++) {
            uint32_t ah_[4], al_[4];
            ldsm_x4(ah_, qaddr + ks * 32);
            ldsm_x4(al_, qaddr + 18432 + ks * 32);
            #pragma unroll
            for (int p = 0; p < 4; p++) {
                uint32_t bh_[4], bl_[4];
                uint32_t ka = kaddr + p * 2304 + ks * 32;
                ldsm_x4(bh_, ka);
                ldsm_x4(bl_, ka + 9216);
                mma16816(acc[2*p],     ah_, bh_);
                mma16816(acc[2*p],     al_, bh_);
                mma16816(acc[2*p],     ah_, bl_);
                mma16816(acc[2*p + 1], ah_, bh_ + 2);
                mma16816(acc[2*p + 1], al_, bh_ + 2);
                mma16816(acc[2*p + 1], ah_, bl_ + 2);
            }
        }

        // ---- mask + exp + store e + rowsums ----
        const int* mskj = (const int*)(smem + S_MSK + (j & 1) * 256);
        const int kt0 = j * TK;
        const bool dtile = (j >= 2 * qt);     // tiles that intersect the diagonal
        const int ra = qt * TILE + m0w + g, rb = ra + 8;
        float* rowa = attnrow + (size_t)(m0w + g) * SEQ + kt0;
        float* rowb = rowa + (size_t)8 * SEQ;
        #pragma unroll
        for (int nt = 0; nt < 8; nt++) {
            int lc = nt * 8 + t2, gc = kt0 + lc;
            bool k0 = mskj[lc] != 0, k1 = mskj[lc + 1] != 0;
            float e0 = (k0 && (!dtile || gc     <= ra)) ? __expf(acc[nt][0]) : 0.f;
            float e1 = (k1 && (!dtile || gc + 1 <= ra)) ? __expf(acc[nt][1]) : 0.f;
            float e2 = (k0 && (!dtile || gc     <= rb)) ? __expf(acc[nt][2]) : 0.f;
            float e3 = (k1 && (!dtile || gc + 1 <= rb)) ? __expf(acc[nt][3]) : 0.f;
            rs0 += e0 + e1; rs1 += e2 + e3;
            acc[nt][0] = e0; acc[nt][1] = e1; acc[nt][2] = e2; acc[nt][3] = e3;
            *(float2*)(rowa + lc) = make_float2(e0, e1);
            *(float2*)(rowb + lc) = make_float2(e2, e3);
        }

        // ---- P·V: repack e-frags (C-layout -> A-layout), accumulate out ----
        #pragma unroll
        for (int ks = 0; ks < 4; ks++) {
            uint32_t eh[4], el[4];
            pack_split(acc[2*ks][0],     acc[2*ks][1],     eh[0], el[0]);
            pack_split(acc[2*ks][2],     acc[2*ks][3],     eh[1], el[1]);
            pack_split(acc[2*ks + 1][0], acc[2*ks + 1][1], eh[2], el[2]);
            pack_split(acc[2*ks + 1][2], acc[2*ks + 1][3], eh[3], el[3]);
            #pragma unroll
            for (int p = 0; p < 4; p++) {
                uint32_t vh_[4], vl_[4];
                uint32_t va = vaddr + ks * 2304 + p * 32;
                ldsm_x4t(vh_, va);
                ldsm_x4t(vl_, va + 9216);
                mma16816(acc_o[2*p],     eh, vh_);
                mma16816(acc_o[2*p],     el, vh_);
                mma16816(acc_o[2*p],     eh, vl_);
                mma16816(acc_o[2*p + 1], eh, vh_ + 2);
                mma16816(acc_o[2*p + 1], el, vh_ + 2);
                mma16816(acc_o[2*p + 1], eh, vl_ + 2);
            }
        }
    }

    // ---- rowsum reduce -> invl ----
    rs0 += __shfl_xor_sync(0xFFFFFFFFu, rs0, 1);
    rs0 += __shfl_xor_sync(0xFFFFFFFFu, rs0, 2);
    rs1 += __shfl_xor_sync(0xFFFFFFFFu, rs1, 1);
    rs1 += __shfl_xor_sync(0xFFFFFFFFu, rs1, 2);
    if ((lane & 3) == 0) {
        invl[m0w + g]     = 1.0f / rs0;
        invl[m0w + g + 8] = 1.0f / rs1;
    }
    __syncthreads();

    // ---- write out = acc_o * invl ----
    float* obase = out + ((size_t)bh * SEQ + (size_t)qt * TILE) * HDIM;
    const float il0 = invl[m0w + g], il1 = invl[m0w + g + 8];
    #pragma unroll
    for (int nt = 0; nt < 8; nt++) {
        int c = nt * 8 + t2;
        *(float2*)&obase[(size_t)(m0w + g) * HDIM + c] =
            make_float2(acc_o[nt][0] * il0, acc_o[nt][1] * il0);
        *(float2*)&obase[(size_t)(m0w + g + 8) * HDIM + c] =
            make_float2(acc_o[nt][2] * il1, acc_o[nt][3] * il1);
    }

    // ---- streaming phase: p = e * invl in place, zero upper triangle ----
    const int lim4 = (qt + 1) * TILE / 4;
    for (int i = tid; i < TILE * (SEQ / 4); i += 256) {
        int r = i >> 9, c4 = i & 511;
        float4* pp = (float4*)&attnrow[(size_t)r * SEQ] + c4;
        if (c4 < lim4) {
            float4 e = *pp;
            float il = invl[r];
            e.x *= il; e.y *= il; e.z *= il; e.w *= il;
            *pp = e;
        } else {
            *pp = make_float4(0.f, 0.f, 0.f, 0.f);
        }
    }
}

// ---------------------------------------------------------------------------
extern "C" void kernel_launch(void* const* d_in, const int* in_sizes, int n_in,
                              void* d_out, int out_size)
{
    const float* q    = (const float*)d_in[0];
    const float* k    = (const float*)d_in[1];
    const float* v    = (const float*)d_in[2];
    const int*   mask = (const int*)d_in[3];

    float* out  = (float*)d_out;                       // [B,H,S,D]
    float* attn = out + (size_t)BH * SEQ * HDIM;       // [B,H,S,S]

    cudaFuncSetAttribute(fused_attn, cudaFuncAttributeMaxDynamicSharedMemorySize, S_SZ);

    dim3 grid(NT, BH);
    fused_attn<<<grid, 256, S_SZ>>>(q, k, v, mask, out, attn);
}

// round 6
// speedup vs baseline: 1.9427x; 1.0771x over previous
#include <cuda_runtime.h>
#include <cuda_bf16.h>
#include <cstdint>

// B=2,H=16,S=2048,D=64 fp32 causal attention; d_out = out[B,H,S,D] ++ attn[B,H,S,S]
#define SEQ   2048
#define HDIM  64
#define BH    32
#define TILE  128               // q-tile rows per CTA
#define TK    64                // kv-tile rows per pipeline step
#define NT    (SEQ / TILE)      // 16

// smem layout (bytes)
#define S_QH   0                // 128*72*2 = 18432
#define S_QL   18432
#define S_KH   36864            // 64*72*2 = 9216
#define S_KL   46080
#define S_VH   55296
#define S_VL   64512
#define S_RAWK 73728            // 64*64*4 = 16384
#define S_RAWV 90112
#define S_MSK  106496           // 2 x 256B (double buffered)
#define S_INV  107008           // 128 floats
#define S_SZ   107520

// q pre-scale: 1/temperature * log2(e)  (epilogue uses ex2)
#define QSCALE (0.125f * 1.44269504088896341f)

// ---------------------------------------------------------------------------
__device__ __forceinline__ uint32_t smem_u32(const void* p) {
    uint32_t a;
    asm("{ .reg .u64 t; cvta.to.shared.u64 t, %1; cvt.u32.u64 %0, t; }" : "=r"(a) : "l"(p));
    return a;
}
__device__ __forceinline__ void ldsm_x4(uint32_t* r, uint32_t a) {
    asm volatile("ldmatrix.sync.aligned.m8n8.x4.shared.b16 {%0,%1,%2,%3}, [%4];"
        : "=r"(r[0]), "=r"(r[1]), "=r"(r[2]), "=r"(r[3]) : "r"(a));
}
__device__ __forceinline__ void ldsm_x4t(uint32_t* r, uint32_t a) {
    asm volatile("ldmatrix.sync.aligned.m8n8.x4.trans.shared.b16 {%0,%1,%2,%3}, [%4];"
        : "=r"(r[0]), "=r"(r[1]), "=r"(r[2]), "=r"(r[3]) : "r"(a));
}
__device__ __forceinline__ void mma16816(float* c, const uint32_t* a, const uint32_t* b) {
    asm volatile("mma.sync.aligned.m16n8k16.row.col.f32.bf16.bf16.f32 "
        "{%0,%1,%2,%3}, {%4,%5,%6,%7}, {%8,%9}, {%0,%1,%2,%3};"
        : "+f"(c[0]), "+f"(c[1]), "+f"(c[2]), "+f"(c[3])
        : "r"(a[0]), "r"(a[1]), "r"(a[2]), "r"(a[3]), "r"(b[0]), "r"(b[1]));
}
__device__ __forceinline__ void cp16(uint32_t s, const void* g) {
    asm volatile("cp.async.cg.shared.global [%0], [%1], 16;" :: "r"(s), "l"(g));
}
#define CP_COMMIT() asm volatile("cp.async.commit_group;" ::: "memory")
#define CP_WAIT0()  asm volatile("cp.async.wait_group 0;" ::: "memory")

__device__ __forceinline__ float ex2(float x) {
    float y; asm("ex2.approx.f32 %0, %1;" : "=f"(y) : "f"(x)); return y;
}
__device__ __forceinline__ __nv_bfloat162 split2(float2 x, __nv_bfloat162* lo) {
    __nv_bfloat16 hx = __float2bfloat16(x.x), hy = __float2bfloat16(x.y);
    lo->x = __float2bfloat16(x.x - __bfloat162float(hx));
    lo->y = __float2bfloat16(x.y - __bfloat162float(hy));
    __nv_bfloat162 h; h.x = hx; h.y = hy; return h;
}
__device__ __forceinline__ void pack_split(float x, float y, uint32_t& h, uint32_t& l) {
    __nv_bfloat162 hv, lv;
    hv = split2(make_float2(x, y), &lv);
    h = *reinterpret_cast<uint32_t*>(&hv);
    l = *reinterpret_cast<uint32_t*>(&lv);
}
__device__ __forceinline__ uint32_t u32of(__nv_bfloat162 v) {
    return *reinterpret_cast<uint32_t*>(&v);
}

// ---------------------------------------------------------------------------
// Fused causal attention: pass1 rowsums, pass2 normalized p + PV.
// 256 thr = 8 warps, warp tile 16 x 64.
// ---------------------------------------------------------------------------
__global__ void __launch_bounds__(256, 2)
fused_attn(const float* __restrict__ q, const float* __restrict__ k,
           const float* __restrict__ v, const int* __restrict__ mask,
           float* __restrict__ out, float* __restrict__ attn)
{
    extern __shared__ char smem[];
    const int qt  = (NT - 1) - blockIdx.x;   // heavy tiles first
    const int bh  = blockIdx.y, b = bh >> 4;
    const int tid = threadIdx.x, wid = tid >> 5, lane = tid & 31;
    const int g = lane >> 2, t2 = (lane & 3) << 1;
    const int m0w = wid * 16;

    __nv_bfloat16* qh = (__nv_bfloat16*)(smem + S_QH);
    __nv_bfloat16* ql = (__nv_bfloat16*)(smem + S_QL);
    __nv_bfloat16* kh = (__nv_bfloat16*)(smem + S_KH);
    __nv_bfloat16* kl = (__nv_bfloat16*)(smem + S_KL);
    __nv_bfloat16* vh = (__nv_bfloat16*)(smem + S_VH);
    __nv_bfloat16* vl = (__nv_bfloat16*)(smem + S_VL);
    float* invl = (float*)(smem + S_INV);
    const uint32_t sb = smem_u32(smem);

    const uint32_t qaddr = sb + S_QH +
        (uint32_t)(((m0w + (lane & 15)) * 72 + ((lane >> 4) & 1) * 8) * 2);
    const uint32_t kaddr = sb + S_KH +
        (uint32_t)((((lane & 7) + ((lane >> 4) & 1) * 8) * 72 + ((lane >> 3) & 1) * 8) * 2);
    const uint32_t vaddr = sb + S_VH +
        (uint32_t)(((lane & 15) * 72 + ((lane >> 4) & 1) * 8) * 2);

    float* attnrow = attn + (size_t)bh * SEQ * SEQ + (size_t)qt * TILE * SEQ;
    const int* mrow = mask + b * SEQ;
    const float* kbh = k + (size_t)bh * SEQ * HDIM;
    const float* vbh = v + (size_t)bh * SEQ * HDIM;
    const int nkt = 2 * qt + 2;

    // ---- 0) zero the strictly-upper tiles first (drains under compute) ----
    {
        const int zc0 = ((qt + 1) * TILE) >> 2;   // first float4 col to zero
        const float4 z = make_float4(0.f, 0.f, 0.f, 0.f);
        float4* zbase = (float4*)attnrow;
        for (int r = tid >> 3; r < TILE; r += 32) {
            float4* rowp = zbase + (size_t)r * (SEQ / 4);
            for (int c = zc0 + (lane & 7); c < SEQ / 4; c += 8)
                rowp[c] = z;
        }
    }

    // ---- 1) stage Q (scaled for ex2) hi/lo, row stride 72 bf16 ----
    const float* qbase = q + ((size_t)bh * SEQ + (size_t)qt * TILE) * HDIM;
    for (int i = tid; i < TILE * HDIM / 2; i += 256) {
        int r = i >> 5, c2 = (i & 31) << 1;
        float2 x = *(const float2*)&qbase[r * HDIM + c2];
        x.x *= QSCALE; x.y *= QSCALE;
        __nv_bfloat162 lo, hi = split2(x, &lo);
        *(__nv_bfloat162*)&qh[r * 72 + c2] = hi;
        *(__nv_bfloat162*)&ql[r * 72 + c2] = lo;
    }

    const int ra = qt * TILE + m0w + g, rb = ra + 8;
    float rs0 = 0.f, rs1 = 0.f;

    // ================= PASS 1: rowsums only (K traffic only) ==============
    {
        #pragma unroll
        for (int t = 0; t < 4; t++) {
            int idx = tid + t * 256;
            cp16(sb + S_RAWK + idx * 16, (const char*)kbh + idx * 16);
        }
        if (tid < 16) cp16(sb + S_MSK + tid * 16, mrow + tid * 4);
        CP_COMMIT();
    }
    for (int j = 0; j < nkt; ++j) {
        CP_WAIT0();
        __syncthreads();
        {   // convert raw K -> bf16 hi/lo
            const float4* rk = (const float4*)(smem + S_RAWK);
            #pragma unroll
            for (int t = 0; t < 4; t++) {
                int idx = tid + t * 256;
                int r = idx >> 4, c4 = (idx & 15) << 2;
                float4 xk = rk[idx];
                __nv_bfloat162 l0, h0 = split2(make_float2(xk.x, xk.y), &l0);
                __nv_bfloat162 l1, h1 = split2(make_float2(xk.z, xk.w), &l1);
                *(uint2*)&kh[r * 72 + c4] = make_uint2(u32of(h0), u32of(h1));
                *(uint2*)&kl[r * 72 + c4] = make_uint2(u32of(l0), u32of(l1));
            }
        }
        __syncthreads();
        if (j + 1 < nkt) {
            const char* kg = (const char*)(kbh + (size_t)(j + 1) * TK * HDIM);
            #pragma unroll
            for (int t = 0; t < 4; t++) {
                int idx = tid + t * 256;
                cp16(sb + S_RAWK + idx * 16, kg + idx * 16);
            }
            if (tid < 16)
                cp16(sb + S_MSK + ((j + 1) & 1) * 256 + tid * 16,
                     mrow + (j + 1) * TK + tid * 4);
        }
        CP_COMMIT();

        float acc[8][4];
        #pragma unroll
        for (int nt = 0; nt < 8; nt++)
            #pragma unroll
            for (int jj = 0; jj < 4; jj++) acc[nt][jj] = 0.f;
        #pragma unroll
        for (int ks = 0; ks < 4; ks++) {
            uint32_t ah_[4], al_[4];
            ldsm_x4(ah_, qaddr + ks * 32);
            ldsm_x4(al_, qaddr + 18432 + ks * 32);
            #pragma unroll
            for (int p = 0; p < 4; p++) {
                uint32_t bh_[4], bl_[4];
                uint32_t ka = kaddr + p * 2304 + ks * 32;
                ldsm_x4(bh_, ka);
                ldsm_x4(bl_, ka + 9216);
                mma16816(acc[2*p],     ah_, bh_);
                mma16816(acc[2*p],     al_, bh_);
                mma16816(acc[2*p],     ah_, bl_);
                mma16816(acc[2*p + 1], ah_, bh_ + 2);
                mma16816(acc[2*p + 1], al_, bh_ + 2);
                mma16816(acc[2*p + 1], ah_, bl_ + 2);
            }
        }

        const int* mskj = (const int*)(smem + S_MSK + (j & 1) * 256);
        const int kt0 = j * TK;
        const bool dtile = (j >= 2 * qt);
        #pragma unroll
        for (int nt = 0; nt < 8; nt++) {
            int lc = nt * 8 + t2, gc = kt0 + lc;
            bool k0 = mskj[lc] != 0, k1 = mskj[lc + 1] != 0;
            float e0 = (k0 && (!dtile || gc     <= ra)) ? ex2(acc[nt][0]) : 0.f;
            float e1 = (k1 && (!dtile || gc + 1 <= ra)) ? ex2(acc[nt][1]) : 0.f;
            float e2 = (k0 && (!dtile || gc     <= rb)) ? ex2(acc[nt][2]) : 0.f;
            float e3 = (k1 && (!dtile || gc + 1 <= rb)) ? ex2(acc[nt][3]) : 0.f;
            rs0 += e0 + e1; rs1 += e2 + e3;
        }
    }

    // ---- between passes: issue pass-2 tile 0, reduce rowsums -> invl ----
    __syncthreads();   // all pass-1 smem reads done
    {
        #pragma unroll
        for (int t = 0; t < 4; t++) {
            int idx = tid + t * 256;
            cp16(sb + S_RAWK + idx * 16, (const char*)kbh + idx * 16);
            cp16(sb + S_RAWV + idx * 16, (const char*)vbh + idx * 16);
        }
        if (tid < 16) cp16(sb + S_MSK + tid * 16, mrow + tid * 4);
        CP_COMMIT();
    }
    rs0 += __shfl_xor_sync(0xFFFFFFFFu, rs0, 1);
    rs0 += __shfl_xor_sync(0xFFFFFFFFu, rs0, 2);
    rs1 += __shfl_xor_sync(0xFFFFFFFFu, rs1, 1);
    rs1 += __shfl_xor_sync(0xFFFFFFFFu, rs1, 2);
    if ((lane & 3) == 0) {
        invl[m0w + g]     = 1.0f / rs0;
        invl[m0w + g + 8] = 1.0f / rs1;
    }
    __syncthreads();
    const float il0 = invl[m0w + g], il1 = invl[m0w + g + 8];

    float acc_o[8][4];
    #pragma unroll
    for (int nt = 0; nt < 8; nt++)
        #pragma unroll
        for (int jj = 0; jj < 4; jj++) acc_o[nt][jj] = 0.f;

    // ================= PASS 2: normalized p store + PV =====================
    for (int j = 0; j < nkt; ++j) {
        CP_WAIT0();
        __syncthreads();
        {   // convert raw K+V -> bf16 hi/lo
            const float4* rk = (const float4*)(smem + S_RAWK);
            const float4* rv = (const float4*)(smem + S_RAWV);
            #pragma unroll
            for (int t = 0; t < 4; t++) {
                int idx = tid + t * 256;
                int r = idx >> 4, c4 = (idx & 15) << 2;
                float4 xk = rk[idx];
                float4 xv = rv[idx];
                __nv_bfloat162 kl0, kh0 = split2(make_float2(xk.x, xk.y), &kl0);
                __nv_bfloat162 kl1, kh1 = split2(make_float2(xk.z, xk.w), &kl1);
                __nv_bfloat162 vl0, vh0 = split2(make_float2(xv.x, xv.y), &vl0);
                __nv_bfloat162 vl1, vh1 = split2(make_float2(xv.z, xv.w), &vl1);
                *(uint2*)&kh[r * 72 + c4] = make_uint2(u32of(kh0), u32of(kh1));
                *(uint2*)&kl[r * 72 + c4] = make_uint2(u32of(kl0), u32of(kl1));
                *(uint2*)&vh[r * 72 + c4] = make_uint2(u32of(vh0), u32of(vh1));
                *(uint2*)&vl[r * 72 + c4] = make_uint2(u32of(vl0), u32of(vl1));
            }
        }
        __syncthreads();
        if (j + 1 < nkt) {
            const char* kg = (const char*)(kbh + (size_t)(j + 1) * TK * HDIM);
            const char* vg = (const char*)(vbh + (size_t)(j + 1) * TK * HDIM);
            #pragma unroll
            for (int t = 0; t < 4; t++) {
                int idx = tid + t * 256;
                cp16(sb + S_RAWK + idx * 16, kg + idx * 16);
                cp16(sb + S_RAWV + idx * 16, vg + idx * 16);
            }
            if (tid < 16)
                cp16(sb + S_MSK + ((j + 1) & 1) * 256 + tid * 16,
                     mrow + (j + 1) * TK + tid * 4);
        }
        CP_COMMIT();

        // ---- QK^T (identical instruction sequence to pass 1) ----
        float acc[8][4];
        #pragma unroll
        for (int nt = 0; nt < 8; nt++)
            #pragma unroll
            for (int jj = 0; jj < 4; jj++) acc[nt][jj] = 0.f;
        #pragma unroll
        for (int ks = 0; ks < 4; ks++) {
            uint32_t ah_[4], al_[4];
            ldsm_x4(ah_, qaddr + ks * 32);
            ldsm_x4(al_, qaddr + 18432 + ks * 32);
            #pragma unroll
            for (int p = 0; p < 4; p++) {
                uint32_t bh_[4], bl_[4];
                uint32_t ka = kaddr + p * 2304 + ks * 32;
                ldsm_x4(bh_, ka);
                ldsm_x4(bl_, ka + 9216);
                mma16816(acc[2*p],     ah_, bh_);
                mma16816(acc[2*p],     al_, bh_);
                mma16816(acc[2*p],     ah_, bl_);
                mma16816(acc[2*p + 1], ah_, bh_ + 2);
                mma16816(acc[2*p + 1], al_, bh_ + 2);
                mma16816(acc[2*p + 1], ah_, bl_ + 2);
            }
        }

        // ---- exp, normalize, store p ----
        const int* mskj = (const int*)(smem + S_MSK + (j & 1) * 256);
        const int kt0 = j * TK;
        const bool dtile = (j >= 2 * qt);
        float* rowa = attnrow + (size_t)(m0w + g) * SEQ + kt0;
        float* rowb = rowa + (size_t)8 * SEQ;
        #pragma unroll
        for (int nt = 0; nt < 8; nt++) {
            int lc = nt * 8 + t2, gc = kt0 + lc;
            bool k0 = mskj[lc] != 0, k1 = mskj[lc + 1] != 0;
            float e0 = (k0 && (!dtile || gc     <= ra)) ? ex2(acc[nt][0]) : 0.f;
            float e1 = (k1 && (!dtile || gc + 1 <= ra)) ? ex2(acc[nt][1]) : 0.f;
            float e2 = (k0 && (!dtile || gc     <= rb)) ? ex2(acc[nt][2]) : 0.f;
            float e3 = (k1 && (!dtile || gc + 1 <= rb)) ? ex2(acc[nt][3]) : 0.f;
            e0 *= il0; e1 *= il0; e2 *= il1; e3 *= il1;
            acc[nt][0] = e0; acc[nt][1] = e1; acc[nt][2] = e2; acc[nt][3] = e3;
            *(float2*)(rowa + lc) = make_float2(e0, e1);
            *(float2*)(rowb + lc) = make_float2(e2, e3);
        }

        // ---- P·V with normalized p fragments ----
        #pragma unroll
        for (int ks = 0; ks < 4; ks++) {
            uint32_t eh[4], el[4];
            pack_split(acc[2*ks][0],     acc[2*ks][1],     eh[0], el[0]);
            pack_split(acc[2*ks][2],     acc[2*ks][3],     eh[1], el[1]);
            pack_split(acc[2*ks + 1][0], acc[2*ks + 1][1], eh[2], el[2]);
            pack_split(acc[2*ks + 1][2], acc[2*ks + 1][3], eh[3], el[3]);
            #pragma unroll
            for (int p = 0; p < 4; p++) {
                uint32_t vh_[4], vl_[4];
                uint32_t va = vaddr + ks * 2304 + p * 32;
                ldsm_x4t(vh_, va);
                ldsm_x4t(vl_, va + 9216);
                mma16816(acc_o[2*p],     eh, vh_);
                mma16816(acc_o[2*p],     el, vh_);
                mma16816(acc_o[2*p],     eh, vl_);
                mma16816(acc_o[2*p + 1], eh, vh_ + 2);
                mma16816(acc_o[2*p + 1], el, vh_ + 2);
                mma16816(acc_o[2*p + 1], eh, vl_ + 2);
            }
        }
    }

    // ---- out = acc_o (already normalized) ----
    float* obase = out + ((size_t)bh * SEQ + (size_t)qt * TILE) * HDIM;
    #pragma unroll
    for (int nt = 0; nt < 8; nt++) {
        int c = nt * 8 + t2;
        *(float2*)&obase[(size_t)(m0w + g) * HDIM + c] =
            make_float2(acc_o[nt][0], acc_o[nt][1]);
        *(float2*)&obase[(size_t)(m0w + g + 8) * HDIM + c] =
            make_float2(acc_o[nt][2], acc_o[nt][3]);
    }
}

// ---------------------------------------------------------------------------
extern "C" void kernel_launch(void* const* d_in, const int* in_sizes, int n_in,
                              void* d_out, int out_size)
{
    const float* q    = (const float*)d_in[0];
    const float* k    = (const float*)d_in[1];
    const float* v    = (const float*)d_in[2];
    const int*   mask = (const int*)d_in[3];

    float* out  = (float*)d_out;                       // [B,H,S,D]
    float* attn = out + (size_t)BH * SEQ * HDIM;       // [B,H,S,S]

    cudaFuncSetAttribute(fused_attn, cudaFuncAttributeMaxDynamicSharedMemorySize, S_SZ);

    dim3 grid(NT, BH);
    fused_attn<<<grid, 256, S_SZ>>>(q, k, v, mask, out, attn);
}

// round 7
// speedup vs baseline: 2.1225x; 1.0926x over previous
#include <cuda_runtime.h>
#include <cuda_bf16.h>
#include <cstdint>

// B=2,H=16,S=2048,D=64 fp32 causal attention; d_out = out[B,H,S,D] ++ attn[B,H,S,S]
#define SEQ   2048
#define HDIM  64
#define BH    32
#define TILE  128               // q-tile rows per CTA
#define TK    64                // kv-tile rows per pipeline step
#define NT    (SEQ / TILE)      // 16
#define NELEM (BH * SEQ * HDIM) // 4,194,304

// q pre-scale: 1/temperature * log2(e)  (epilogue uses ex2)
#define QSCALE (0.125f * 1.44269504088896341f)

// precomputed bf16 hi/lo splits (prep kernel fills these)
__device__ __align__(16) __nv_bfloat16 g_qh[NELEM];
__device__ __align__(16) __nv_bfloat16 g_ql[NELEM];
__device__ __align__(16) __nv_bfloat16 g_kh[NELEM];
__device__ __align__(16) __nv_bfloat16 g_kl[NELEM];
__device__ __align__(16) __nv_bfloat16 g_vh[NELEM];
__device__ __align__(16) __nv_bfloat16 g_vl[NELEM];

// smem layout (bytes). Q overlays the stage area during the prologue.
// stage st at S_ST + st*36864: KH +0, KL +9216, VH +18432, VL +27648
#define S_ST   0
#define S_MSK  73728            // 2 x 256B (double buffered)
#define S_INV  74240            // 128 floats
#define S_SZ   74752

// ---------------------------------------------------------------------------
__device__ __forceinline__ uint32_t smem_u32(const void* p) {
    uint32_t a;
    asm("{ .reg .u64 t; cvta.to.shared.u64 t, %1; cvt.u32.u64 %0, t; }" : "=r"(a) : "l"(p));
    return a;
}
__device__ __forceinline__ void ldsm_x4(uint32_t* r, uint32_t a) {
    asm volatile("ldmatrix.sync.aligned.m8n8.x4.shared.b16 {%0,%1,%2,%3}, [%4];"
        : "=r"(r[0]), "=r"(r[1]), "=r"(r[2]), "=r"(r[3]) : "r"(a));
}
__device__ __forceinline__ void ldsm_x4t(uint32_t* r, uint32_t a) {
    asm volatile("ldmatrix.sync.aligned.m8n8.x4.trans.shared.b16 {%0,%1,%2,%3}, [%4];"
        : "=r"(r[0]), "=r"(r[1]), "=r"(r[2]), "=r"(r[3]) : "r"(a));
}
__device__ __forceinline__ void mma16816(float* c, const uint32_t* a, const uint32_t* b) {
    asm volatile("mma.sync.aligned.m16n8k16.row.col.f32.bf16.bf16.f32 "
        "{%0,%1,%2,%3}, {%4,%5,%6,%7}, {%8,%9}, {%0,%1,%2,%3};"
        : "+f"(c[0]), "+f"(c[1]), "+f"(c[2]), "+f"(c[3])
        : "r"(a[0]), "r"(a[1]), "r"(a[2]), "r"(a[3]), "r"(b[0]), "r"(b[1]));
}
__device__ __forceinline__ void cp16(uint32_t s, const void* g) {
    asm volatile("cp.async.cg.shared.global [%0], [%1], 16;" :: "r"(s), "l"(g));
}
#define CP_COMMIT() asm volatile("cp.async.commit_group;" ::: "memory")
#define CP_WAIT0()  asm volatile("cp.async.wait_group 0;" ::: "memory")

__device__ __forceinline__ float ex2(float x) {
    float y; asm("ex2.approx.f32 %0, %1;" : "=f"(y) : "f"(x)); return y;
}
__device__ __forceinline__ void pack_split(float x, float y, uint32_t& h, uint32_t& l) {
    __nv_bfloat16 hx = __float2bfloat16(x), hy = __float2bfloat16(y);
    __nv_bfloat162 hv; hv.x = hx; hv.y = hy;
    __nv_bfloat162 lv;
    lv.x = __float2bfloat16(x - __bfloat162float(hx));
    lv.y = __float2bfloat16(y - __bfloat162float(hy));
    h = *reinterpret_cast<uint32_t*>(&hv);
    l = *reinterpret_cast<uint32_t*>(&lv);
}

// ---------------------------------------------------------------------------
// Preprocess: split q (scaled), k, v into bf16 hi/lo global buffers.
// 8 elements per thread; grid covers NELEM/8 threads exactly.
// ---------------------------------------------------------------------------
__global__ void __launch_bounds__(256)
prep(const float* __restrict__ q, const float* __restrict__ k,
     const float* __restrict__ v)
{
    size_t i = ((size_t)blockIdx.x * 256 + threadIdx.x) * 8;
    {
        float4 a = *(const float4*)(q + i), b = *(const float4*)(q + i + 4);
        a.x *= QSCALE; a.y *= QSCALE; a.z *= QSCALE; a.w *= QSCALE;
        b.x *= QSCALE; b.y *= QSCALE; b.z *= QSCALE; b.w *= QSCALE;
        uint4 h, l;
        pack_split(a.x, a.y, h.x, l.x); pack_split(a.z, a.w, h.y, l.y);
        pack_split(b.x, b.y, h.z, l.z); pack_split(b.z, b.w, h.w, l.w);
        *(uint4*)(g_qh + i) = h; *(uint4*)(g_ql + i) = l;
    }
    {
        float4 a = *(const float4*)(k + i), b = *(const float4*)(k + i + 4);
        uint4 h, l;
        pack_split(a.x, a.y, h.x, l.x); pack_split(a.z, a.w, h.y, l.y);
        pack_split(b.x, b.y, h.z, l.z); pack_split(b.z, b.w, h.w, l.w);
        *(uint4*)(g_kh + i) = h; *(uint4*)(g_kl + i) = l;
    }
    {
        float4 a = *(const float4*)(v + i), b = *(const float4*)(v + i + 4);
        uint4 h, l;
        pack_split(a.x, a.y, h.x, l.x); pack_split(a.z, a.w, h.y, l.y);
        pack_split(b.x, b.y, h.z, l.z); pack_split(b.z, b.w, h.w, l.w);
        *(uint4*)(g_vh + i) = h; *(uint4*)(g_vl + i) = l;
    }
}

// load a 64x64 bf16 tile (row = 128B contiguous) into smem with 144B row stride
#define LOADT(dstbase, gsrc) do { \
    const char* _g = (const char*)(gsrc); \
    _Pragma("unroll") \
    for (int _t = 0; _t < 2; _t++) { \
        int _i = tid + _t * 256, _r = _i >> 3, _c = _i & 7; \
        cp16((dstbase) + _r * 144 + _c * 16, _g + _r * 128 + _c * 16); \
    } \
} while (0)

// ---------------------------------------------------------------------------
// Fused causal attention: pass1 rowsums, pass2 normalized p + PV.
// 256 thr = 8 warps, warp tile 16 x 64. Q fragments register-resident.
// ---------------------------------------------------------------------------
__global__ void __launch_bounds__(256, 2)
fused_attn(const int* __restrict__ mask, float* __restrict__ out,
           float* __restrict__ attn)
{
    extern __shared__ char smem[];
    const int qt  = (NT - 1) - blockIdx.x;   // heavy tiles first
    const int bh  = blockIdx.y, b = bh >> 4;
    const int tid = threadIdx.x, wid = tid >> 5, lane = tid & 31;
    const int g = lane >> 2, t2 = (lane & 3) << 1;
    const int m0w = wid * 16;

    float* invl = (float*)(smem + S_INV);
    const uint32_t sb = smem_u32(smem);

    // relative ldmatrix offsets within a stage
    const uint32_t koff = (uint32_t)((((lane & 7) + ((lane >> 4) & 1) * 8) * 72
                                     + ((lane >> 3) & 1) * 8) * 2);
    const uint32_t voff = (uint32_t)(((lane & 15) * 72 + ((lane >> 4) & 1) * 8) * 2);

    float* attnrow = attn + (size_t)bh * SEQ * SEQ + (size_t)qt * TILE * SEQ;
    const int* mrow = mask + b * SEQ;
    const size_t plane = (size_t)bh * SEQ * HDIM;
    const int nkt = 2 * qt + 2;

    // ---- 0) zero the strictly-upper tiles first (drains under compute) ----
    {
        const int zc0 = ((qt + 1) * TILE) >> 2;
        const float4 z = make_float4(0.f, 0.f, 0.f, 0.f);
        float4* zbase = (float4*)attnrow;
        for (int r = tid >> 3; r < TILE; r += 32) {
            float4* rowp = zbase + (size_t)r * (SEQ / 4);
            for (int c = zc0 + (lane & 7); c < SEQ / 4; c += 8)
                rowp[c] = z;
        }
    }

    // ---- 1) prologue: load Q tile into stage area, hoist fragments ----
    uint32_t qfh[4][4], qfl[4][4];
    {
        const char* gq = (const char*)(g_qh + plane + (size_t)qt * TILE * HDIM);
        const char* gl = (const char*)(g_ql + plane + (size_t)qt * TILE * HDIM);
        #pragma unroll
        for (int t = 0; t < 4; t++) {
            int i = tid + t * 256, r = i >> 3, c = i & 7;
            cp16(sb + r * 144 + c * 16,         gq + r * 128 + c * 16);
            cp16(sb + 18432 + r * 144 + c * 16, gl + r * 128 + c * 16);
        }
        CP_COMMIT();
        CP_WAIT0();
        __syncthreads();
        const uint32_t qaddr = sb +
            (uint32_t)(((m0w + (lane & 15)) * 72 + ((lane >> 4) & 1) * 8) * 2);
        #pragma unroll
        for (int ks = 0; ks < 4; ks++) {
            ldsm_x4(qfh[ks], qaddr + ks * 32);
            ldsm_x4(qfl[ks], qaddr + 18432 + ks * 32);
        }
        __syncthreads();   // all warps done reading Q smem; stage area reusable
    }

    const int ra = qt * TILE + m0w + g, rb = ra + 8;
    float rs0 = 0.f, rs1 = 0.f;

    // ================= PASS 1: rowsums only (K tiles only) =================
    LOADT(sb + S_ST, g_kh + plane);
    LOADT(sb + S_ST + 9216, g_kl + plane);
    if (tid < 16) cp16(sb + S_MSK + tid * 16, mrow + tid * 4);
    CP_COMMIT();

    for (int j = 0; j < nkt; ++j) {
        CP_WAIT0();
        __syncthreads();
        if (j + 1 < nkt) {
            const uint32_t st1 = sb + S_ST + ((j + 1) & 1) * 36864;
            const size_t tb = plane + (size_t)(j + 1) * TK * HDIM;
            LOADT(st1, g_kh + tb);
            LOADT(st1 + 9216, g_kl + tb);
            if (tid < 16)
                cp16(sb + S_MSK + ((j + 1) & 1) * 256 + tid * 16,
                     mrow + (j + 1) * TK + tid * 4);
            CP_COMMIT();
        }
        const uint32_t kaddr = sb + S_ST + (j & 1) * 36864 + koff;

        float acc[8][4];
        #pragma unroll
        for (int nt = 0; nt < 8; nt++)
            #pragma unroll
            for (int jj = 0; jj < 4; jj++) acc[nt][jj] = 0.f;
        #pragma unroll
        for (int ks = 0; ks < 4; ks++) {
            #pragma unroll
            for (int p = 0; p < 4; p++) {
                uint32_t bh_[4], bl_[4];
                uint32_t ka = kaddr + p * 2304 + ks * 32;
                ldsm_x4(bh_, ka);
                ldsm_x4(bl_, ka + 9216);
                mma16816(acc[2*p],     qfh[ks], bh_);
                mma16816(acc[2*p],     qfl[ks], bh_);
                mma16816(acc[2*p],     qfh[ks], bl_);
                mma16816(acc[2*p + 1], qfh[ks], bh_ + 2);
                mma16816(acc[2*p + 1], qfl[ks], bh_ + 2);
                mma16816(acc[2*p + 1], qfh[ks], bl_ + 2);
            }
        }

        const int* mskj = (const int*)(smem + S_MSK + (j & 1) * 256);
        const int kt0 = j * TK;
        const bool dtile = (j >= 2 * qt);
        #pragma unroll
        for (int nt = 0; nt < 8; nt++) {
            int lc = nt * 8 + t2, gc = kt0 + lc;
            bool k0 = mskj[lc] != 0, k1 = mskj[lc + 1] != 0;
            float e0 = (k0 && (!dtile || gc     <= ra)) ? ex2(acc[nt][0]) : 0.f;
            float e1 = (k1 && (!dtile || gc + 1 <= ra)) ? ex2(acc[nt][1]) : 0.f;
            float e2 = (k0 && (!dtile || gc     <= rb)) ? ex2(acc[nt][2]) : 0.f;
            float e3 = (k1 && (!dtile || gc + 1 <= rb)) ? ex2(acc[nt][3]) : 0.f;
            rs0 += e0 + e1; rs1 += e2 + e3;
        }
    }

    // ---- between passes: preload pass-2 tile 0, reduce rowsums -> invl ----
    __syncthreads();
    {
        const uint32_t st0 = sb + S_ST;
        LOADT(st0, g_kh + plane);
        LOADT(st0 + 9216, g_kl + plane);
        LOADT(st0 + 18432, g_vh + plane);
        LOADT(st0 + 27648, g_vl + plane);
        if (tid < 16) cp16(sb + S_MSK + tid * 16, mrow + tid * 4);
        CP_COMMIT();
    }
    rs0 += __shfl_xor_sync(0xFFFFFFFFu, rs0, 1);
    rs0 += __shfl_xor_sync(0xFFFFFFFFu, rs0, 2);
    rs1 += __shfl_xor_sync(0xFFFFFFFFu, rs1, 1);
    rs1 += __shfl_xor_sync(0xFFFFFFFFu, rs1, 2);
    if ((lane & 3) == 0) {
        invl[m0w + g]     = 1.0f / rs0;
        invl[m0w + g + 8] = 1.0f / rs1;
    }
    __syncthreads();
    const float il0 = invl[m0w + g], il1 = invl[m0w + g + 8];

    float acc_o[8][4];
    #pragma unroll
    for (int nt = 0; nt < 8; nt++)
        #pragma unroll
        for (int jj = 0; jj < 4; jj++) acc_o[nt][jj] = 0.f;

    // ================= PASS 2: normalized p store + PV =====================
    for (int j = 0; j < nkt; ++j) {
        CP_WAIT0();
        __syncthreads();
        if (j + 1 < nkt) {
            const uint32_t st1 = sb + S_ST + ((j + 1) & 1) * 36864;
            const size_t tb = plane + (size_t)(j + 1) * TK * HDIM;
            LOADT(st1, g_kh + tb);
            LOADT(st1 + 9216, g_kl + tb);
            LOADT(st1 + 18432, g_vh + tb);
            LOADT(st1 + 27648, g_vl + tb);
            if (tid < 16)
                cp16(sb + S_MSK + ((j + 1) & 1) * 256 + tid * 16,
                     mrow + (j + 1) * TK + tid * 4);
            CP_COMMIT();
        }
        const uint32_t stb = sb + S_ST + (j & 1) * 36864;
        const uint32_t kaddr = stb + koff;
        const uint32_t vaddr = stb + 18432 + voff;

        // ---- QK^T (identical instruction sequence to pass 1) ----
        float acc[8][4];
        #pragma unroll
        for (int nt = 0; nt < 8; nt++)
            #pragma unroll
            for (int jj = 0; jj < 4; jj++) acc[nt][jj] = 0.f;
        #pragma unroll
        for (int ks = 0; ks < 4; ks++) {
            #pragma unroll
            for (int p = 0; p < 4; p++) {
                uint32_t bh_[4], bl_[4];
                uint32_t ka = kaddr + p * 2304 + ks * 32;
                ldsm_x4(bh_, ka);
                ldsm_x4(bl_, ka + 9216);
                mma16816(acc[2*p],     qfh[ks], bh_);
                mma16816(acc[2*p],     qfl[ks], bh_);
                mma16816(acc[2*p],     qfh[ks], bl_);
                mma16816(acc[2*p + 1], qfh[ks], bh_ + 2);
                mma16816(acc[2*p + 1], qfl[ks], bh_ + 2);
                mma16816(acc[2*p + 1], qfh[ks], bl_ + 2);
            }
        }

        // ---- exp, normalize, store p ----
        const int* mskj = (const int*)(smem + S_MSK + (j & 1) * 256);
        const int kt0 = j * TK;
        const bool dtile = (j >= 2 * qt);
        float* rowa = attnrow + (size_t)(m0w + g) * SEQ + kt0;
        float* rowb = rowa + (size_t)8 * SEQ;
        #pragma unroll
        for (int nt = 0; nt < 8; nt++) {
            int lc = nt * 8 + t2, gc = kt0 + lc;
            bool k0 = mskj[lc] != 0, k1 = mskj[lc + 1] != 0;
            float e0 = (k0 && (!dtile || gc     <= ra)) ? ex2(acc[nt][0]) : 0.f;
            float e1 = (k1 && (!dtile || gc + 1 <= ra)) ? ex2(acc[nt][1]) : 0.f;
            float e2 = (k0 && (!dtile || gc     <= rb)) ? ex2(acc[nt][2]) : 0.f;
            float e3 = (k1 && (!dtile || gc + 1 <= rb)) ? ex2(acc[nt][3]) : 0.f;
            e0 *= il0; e1 *= il0; e2 *= il1; e3 *= il1;
            acc[nt][0] = e0; acc[nt][1] = e1; acc[nt][2] = e2; acc[nt][3] = e3;
            *(float2*)(rowa + lc) = make_float2(e0, e1);
            *(float2*)(rowb + lc) = make_float2(e2, e3);
        }

        // ---- P·V with normalized p fragments ----
        #pragma unroll
        for (int ks = 0; ks < 4; ks++) {
            uint32_t eh[4], el[4];
            pack_split(acc[2*ks][0],     acc[2*ks][1],     eh[0], el[0]);
            pack_split(acc[2*ks][2],     acc[2*ks][3],     eh[1], el[1]);
            pack_split(acc[2*ks + 1][0], acc[2*ks + 1][1], eh[2], el[2]);
            pack_split(acc[2*ks + 1][2], acc[2*ks + 1][3], eh[3], el[3]);
            #pragma unroll
            for (int p = 0; p < 4; p++) {
                uint32_t vh_[4], vl_[4];
                uint32_t va = vaddr + ks * 2304 + p * 32;
                ldsm_x4t(vh_, va);
                ldsm_x4t(vl_, va + 9216);
                mma16816(acc_o[2*p],     eh, vh_);
                mma16816(acc_o[2*p],     el, vh_);
                mma16816(acc_o[2*p],     eh, vl_);
                mma16816(acc_o[2*p + 1], eh, vh_ + 2);
                mma16816(acc_o[2*p + 1], el, vh_ + 2);
                mma16816(acc_o[2*p + 1], eh, vl_ + 2);
            }
        }
    }

    // ---- out = acc_o (already normalized) ----
    float* obase = out + ((size_t)bh * SEQ + (size_t)qt * TILE) * HDIM;
    #pragma unroll
    for (int nt = 0; nt < 8; nt++) {
        int c = nt * 8 + t2;
        *(float2*)&obase[(size_t)(m0w + g) * HDIM + c] =
            make_float2(acc_o[nt][0], acc_o[nt][1]);
        *(float2*)&obase[(size_t)(m0w + g + 8) * HDIM + c] =
            make_float2(acc_o[nt][2], acc_o[nt][3]);
    }
}

// ---------------------------------------------------------------------------
extern "C" void kernel_launch(void* const* d_in, const int* in_sizes, int n_in,
                              void* d_out, int out_size)
{
    const float* q    = (const float*)d_in[0];
    const float* k    = (const float*)d_in[1];
    const float* v    = (const float*)d_in[2];
    const int*   mask = (const int*)d_in[3];

    float* out  = (float*)d_out;                       // [B,H,S,D]
    float* attn = out + (size_t)BH * SEQ * HDIM;       // [B,H,S,S]

    cudaFuncSetAttribute(fused_attn, cudaFuncAttributeMaxDynamicSharedMemorySize, S_SZ);

    prep<<<NELEM / 8 / 256, 256>>>(q, k, v);
    dim3 grid(NT, BH);
    fused_attn<<<grid, 256, S_SZ>>>(mask, out, attn);
}

// round 8
// speedup vs baseline: 2.6346x; 1.2413x over previous
#include <cuda_runtime.h>
#include <cuda_bf16.h>
#include <cstdint>

// B=2,H=16,S=2048,D=64 fp32 causal attention; d_out = out[B,H,S,D] ++ attn[B,H,S,S]
#define SEQ   2048
#define HDIM  64
#define BH    32
#define TILE  128               // q-tile rows per CTA iteration
#define TK    64                // kv-tile rows per pipeline step
#define NT    (SEQ / TILE)      // 16
#define NELEM (BH * SEQ * HDIM) // 4,194,304

// q pre-scale: 1/temperature * log2(e)  (epilogue uses ex2)
#define QSCALE (0.125f * 1.44269504088896341f)

// precomputed bf16 hi/lo splits (prep kernel fills these)
__device__ __align__(16) __nv_bfloat16 g_qh[NELEM];
__device__ __align__(16) __nv_bfloat16 g_ql[NELEM];
__device__ __align__(16) __nv_bfloat16 g_kh[NELEM];
__device__ __align__(16) __nv_bfloat16 g_kl[NELEM];
__device__ __align__(16) __nv_bfloat16 g_vh[NELEM];
__device__ __align__(16) __nv_bfloat16 g_vl[NELEM];

// smem layout (bytes). Q overlays the stage area during the prologue.
// stage st at S_ST + st*36864: KH +0, KL +9216, VH +18432, VL +27648
#define S_ST   0
#define S_MSK  73728            // 2 x 256B (double buffered)
#define S_INV  74240            // 128 floats
#define S_SZ   74752

// ---------------------------------------------------------------------------
__device__ __forceinline__ uint32_t smem_u32(const void* p) {
    uint32_t a;
    asm("{ .reg .u64 t; cvta.to.shared.u64 t, %1; cvt.u32.u64 %0, t; }" : "=r"(a) : "l"(p));
    return a;
}
__device__ __forceinline__ void ldsm_x4(uint32_t* r, uint32_t a) {
    asm volatile("ldmatrix.sync.aligned.m8n8.x4.shared.b16 {%0,%1,%2,%3}, [%4];"
        : "=r"(r[0]), "=r"(r[1]), "=r"(r[2]), "=r"(r[3]) : "r"(a));
}
__device__ __forceinline__ void ldsm_x4t(uint32_t* r, uint32_t a) {
    asm volatile("ldmatrix.sync.aligned.m8n8.x4.trans.shared.b16 {%0,%1,%2,%3}, [%4];"
        : "=r"(r[0]), "=r"(r[1]), "=r"(r[2]), "=r"(r[3]) : "r"(a));
}
__device__ __forceinline__ void mma16816(float* c, const uint32_t* a, const uint32_t* b) {
    asm volatile("mma.sync.aligned.m16n8k16.row.col.f32.bf16.bf16.f32 "
        "{%0,%1,%2,%3}, {%4,%5,%6,%7}, {%8,%9}, {%0,%1,%2,%3};"
        : "+f"(c[0]), "+f"(c[1]), "+f"(c[2]), "+f"(c[3])
        : "r"(a[0]), "r"(a[1]), "r"(a[2]), "r"(a[3]), "r"(b[0]), "r"(b[1]));
}
__device__ __forceinline__ void cp16(uint32_t s, const void* g) {
    asm volatile("cp.async.cg.shared.global [%0], [%1], 16;" :: "r"(s), "l"(g));
}
#define CP_COMMIT() asm volatile("cp.async.commit_group;" ::: "memory")
#define CP_WAIT0()  asm volatile("cp.async.wait_group 0;" ::: "memory")

__device__ __forceinline__ float ex2(float x) {
    float y; asm("ex2.approx.f32 %0, %1;" : "=f"(y) : "f"(x)); return y;
}
__device__ __forceinline__ void pack_split(float x, float y, uint32_t& h, uint32_t& l) {
    __nv_bfloat16 hx = __float2bfloat16(x), hy = __float2bfloat16(y);
    __nv_bfloat162 hv; hv.x = hx; hv.y = hy;
    __nv_bfloat162 lv;
    lv.x = __float2bfloat16(x - __bfloat162float(hx));
    lv.y = __float2bfloat16(y - __bfloat162float(hy));
    h = *reinterpret_cast<uint32_t*>(&hv);
    l = *reinterpret_cast<uint32_t*>(&lv);
}

// ---------------------------------------------------------------------------
// Preprocess: split q (scaled), k, v into bf16 hi/lo global buffers.
// ---------------------------------------------------------------------------
__global__ void __launch_bounds__(256)
prep(const float* __restrict__ q, const float* __restrict__ k,
     const float* __restrict__ v)
{
    size_t i = ((size_t)blockIdx.x * 256 + threadIdx.x) * 8;
    {
        float4 a = *(const float4*)(q + i), b = *(const float4*)(q + i + 4);
        a.x *= QSCALE; a.y *= QSCALE; a.z *= QSCALE; a.w *= QSCALE;
        b.x *= QSCALE; b.y *= QSCALE; b.z *= QSCALE; b.w *= QSCALE;
        uint4 h, l;
        pack_split(a.x, a.y, h.x, l.x); pack_split(a.z, a.w, h.y, l.y);
        pack_split(b.x, b.y, h.z, l.z); pack_split(b.z, b.w, h.w, l.w);
        *(uint4*)(g_qh + i) = h; *(uint4*)(g_ql + i) = l;
    }
    {
        float4 a = *(const float4*)(k + i), b = *(const float4*)(k + i + 4);
        uint4 h, l;
        pack_split(a.x, a.y, h.x, l.x); pack_split(a.z, a.w, h.y, l.y);
        pack_split(b.x, b.y, h.z, l.z); pack_split(b.z, b.w, h.w, l.w);
        *(uint4*)(g_kh + i) = h; *(uint4*)(g_kl + i) = l;
    }
    {
        float4 a = *(const float4*)(v + i), b = *(const float4*)(v + i + 4);
        uint4 h, l;
        pack_split(a.x, a.y, h.x, l.x); pack_split(a.z, a.w, h.y, l.y);
        pack_split(b.x, b.y, h.z, l.z); pack_split(b.z, b.w, h.w, l.w);
        *(uint4*)(g_vh + i) = h; *(uint4*)(g_vl + i) = l;
    }
}

// load a 64x64 bf16 tile (row = 128B contiguous) into smem with 144B row stride
#define LOADT(dstbase, gsrc) do { \
    const char* _g = (const char*)(gsrc); \
    _Pragma("unroll") \
    for (int _t = 0; _t < 2; _t++) { \
        int _i = tid + _t * 256, _r = _i >> 3, _c = _i & 7; \
        cp16((dstbase) + _r * 144 + _c * 16, _g + _r * 128 + _c * 16); \
    } \
} while (0)

// ---------------------------------------------------------------------------
// Fused causal attention, triangle-paired: each CTA handles q-tiles
// qt = NT-1-bx and qt = bx  => uniform 34 kv-tiles per CTA, single wave.
// 256 thr = 8 warps, warp tile 16 x 64. Q fragments register-resident.
// ---------------------------------------------------------------------------
__global__ void __launch_bounds__(256, 2)
fused_attn(const int* __restrict__ mask, float* __restrict__ out,
           float* __restrict__ attn)
{
    extern __shared__ char smem[];
    const int bh  = blockIdx.y, b = bh >> 4;
    const int tid = threadIdx.x, wid = tid >> 5, lane = tid & 31;
    const int g = lane >> 2, t2 = (lane & 3) << 1;
    const int m0w = wid * 16;

    float* invl = (float*)(smem + S_INV);
    const uint32_t sb = smem_u32(smem);

    const uint32_t koff = (uint32_t)((((lane & 7) + ((lane >> 4) & 1) * 8) * 72
                                     + ((lane >> 3) & 1) * 8) * 2);
    const uint32_t voff = (uint32_t)(((lane & 15) * 72 + ((lane >> 4) & 1) * 8) * 2);

    const int* mrow = mask + b * SEQ;
    const size_t plane = (size_t)bh * SEQ * HDIM;

    #pragma unroll 1
    for (int half = 0; half < 2; half++) {
        const int qt = half == 0 ? (NT - 1) - blockIdx.x : blockIdx.x;
        const int nkt = 2 * qt + 2;
        float* attnrow = attn + (size_t)bh * SEQ * SEQ + (size_t)qt * TILE * SEQ;

        // ---- 0) zero the strictly-upper tiles (drains under compute) ----
        {
            const int zc0 = ((qt + 1) * TILE) >> 2;
            const float4 z = make_float4(0.f, 0.f, 0.f, 0.f);
            float4* zbase = (float4*)attnrow;
            for (int r = tid >> 3; r < TILE; r += 32) {
                float4* rowp = zbase + (size_t)r * (SEQ / 4);
                for (int c = zc0 + (lane & 7); c < SEQ / 4; c += 8)
                    rowp[c] = z;
            }
        }

        // ---- 1) prologue: load Q tile into stage area, hoist fragments ----
        uint32_t qfh[4][4], qfl[4][4];
        {
            const char* gq = (const char*)(g_qh + plane + (size_t)qt * TILE * HDIM);
            const char* gl = (const char*)(g_ql + plane + (size_t)qt * TILE * HDIM);
            #pragma unroll
            for (int t = 0; t < 4; t++) {
                int i = tid + t * 256, r = i >> 3, c = i & 7;
                cp16(sb + r * 144 + c * 16,         gq + r * 128 + c * 16);
                cp16(sb + 18432 + r * 144 + c * 16, gl + r * 128 + c * 16);
            }
            CP_COMMIT();
            CP_WAIT0();
            __syncthreads();
            const uint32_t qaddr = sb +
                (uint32_t)(((m0w + (lane & 15)) * 72 + ((lane >> 4) & 1) * 8) * 2);
            #pragma unroll
            for (int ks = 0; ks < 4; ks++) {
                ldsm_x4(qfh[ks], qaddr + ks * 32);
                ldsm_x4(qfl[ks], qaddr + 18432 + ks * 32);
            }
            __syncthreads();   // stage area reusable
        }

        const int ra = qt * TILE + m0w + g, rb = ra + 8;
        float rs0 = 0.f, rs1 = 0.f;

        // ============== PASS 1: rowsums only (K tiles only) ===============
        LOADT(sb + S_ST, g_kh + plane);
        LOADT(sb + S_ST + 9216, g_kl + plane);
        if (tid < 16) cp16(sb + S_MSK + tid * 16, mrow + tid * 4);
        CP_COMMIT();

        for (int j = 0; j < nkt; ++j) {
            CP_WAIT0();
            __syncthreads();
            if (j + 1 < nkt) {
                const uint32_t st1 = sb + S_ST + ((j + 1) & 1) * 36864;
                const size_t tb = plane + (size_t)(j + 1) * TK * HDIM;
                LOADT(st1, g_kh + tb);
                LOADT(st1 + 9216, g_kl + tb);
                if (tid < 16)
                    cp16(sb + S_MSK + ((j + 1) & 1) * 256 + tid * 16,
                         mrow + (j + 1) * TK + tid * 4);
                CP_COMMIT();
            }
            const uint32_t kaddr = sb + S_ST + (j & 1) * 36864 + koff;

            float acc[8][4];
            #pragma unroll
            for (int nt = 0; nt < 8; nt++)
                #pragma unroll
                for (int jj = 0; jj < 4; jj++) acc[nt][jj] = 0.f;
            #pragma unroll
            for (int ks = 0; ks < 4; ks++) {
                #pragma unroll
                for (int p = 0; p < 4; p++) {
                    uint32_t bh_[4], bl_[4];
                    uint32_t ka = kaddr + p * 2304 + ks * 32;
                    ldsm_x4(bh_, ka);
                    ldsm_x4(bl_, ka + 9216);
                    mma16816(acc[2*p],     qfh[ks], bh_);
                    mma16816(acc[2*p],     qfl[ks], bh_);
                    mma16816(acc[2*p],     qfh[ks], bl_);
                    mma16816(acc[2*p + 1], qfh[ks], bh_ + 2);
                    mma16816(acc[2*p + 1], qfl[ks], bh_ + 2);
                    mma16816(acc[2*p + 1], qfh[ks], bl_ + 2);
                }
            }

            const int* mskj = (const int*)(smem + S_MSK + (j & 1) * 256);
            const int kt0 = j * TK;
            const bool dtile = (j >= 2 * qt);
            #pragma unroll
            for (int nt = 0; nt < 8; nt++) {
                int lc = nt * 8 + t2, gc = kt0 + lc;
                bool k0 = mskj[lc] != 0, k1 = mskj[lc + 1] != 0;
                float e0 = (k0 && (!dtile || gc     <= ra)) ? ex2(acc[nt][0]) : 0.f;
                float e1 = (k1 && (!dtile || gc + 1 <= ra)) ? ex2(acc[nt][1]) : 0.f;
                float e2 = (k0 && (!dtile || gc     <= rb)) ? ex2(acc[nt][2]) : 0.f;
                float e3 = (k1 && (!dtile || gc + 1 <= rb)) ? ex2(acc[nt][3]) : 0.f;
                rs0 += e0 + e1; rs1 += e2 + e3;
            }
        }

        // ---- between passes: preload pass-2 tile 0, reduce rowsums ----
        __syncthreads();
        {
            const uint32_t st0 = sb + S_ST;
            LOADT(st0, g_kh + plane);
            LOADT(st0 + 9216, g_kl + plane);
            LOADT(st0 + 18432, g_vh + plane);
            LOADT(st0 + 27648, g_vl + plane);
            if (tid < 16) cp16(sb + S_MSK + tid * 16, mrow + tid * 4);
            CP_COMMIT();
        }
        rs0 += __shfl_xor_sync(0xFFFFFFFFu, rs0, 1);
        rs0 += __shfl_xor_sync(0xFFFFFFFFu, rs0, 2);
        rs1 += __shfl_xor_sync(0xFFFFFFFFu, rs1, 1);
        rs1 += __shfl_xor_sync(0xFFFFFFFFu, rs1, 2);
        if ((lane & 3) == 0) {
            invl[m0w + g]     = 1.0f / rs0;
            invl[m0w + g + 8] = 1.0f / rs1;
        }
        __syncthreads();
        const float il0 = invl[m0w + g], il1 = invl[m0w + g + 8];

        float acc_o[8][4];
        #pragma unroll
        for (int nt = 0; nt < 8; nt++)
            #pragma unroll
            for (int jj = 0; jj < 4; jj++) acc_o[nt][jj] = 0.f;

        // ============== PASS 2: normalized p store + PV ====================
        for (int j = 0; j < nkt; ++j) {
            CP_WAIT0();
            __syncthreads();
            if (j + 1 < nkt) {
                const uint32_t st1 = sb + S_ST + ((j + 1) & 1) * 36864;
                const size_t tb = plane + (size_t)(j + 1) * TK * HDIM;
                LOADT(st1, g_kh + tb);
                LOADT(st1 + 9216, g_kl + tb);
                LOADT(st1 + 18432, g_vh + tb);
                LOADT(st1 + 27648, g_vl + tb);
                if (tid < 16)
                    cp16(sb + S_MSK + ((j + 1) & 1) * 256 + tid * 16,
                         mrow + (j + 1) * TK + tid * 4);
                CP_COMMIT();
            }
            const uint32_t stb = sb + S_ST + (j & 1) * 36864;
            const uint32_t kaddr = stb + koff;
            const uint32_t vaddr = stb + 18432 + voff;

            // ---- QK^T (identical instruction sequence to pass 1) ----
            float acc[8][4];
            #pragma unroll
            for (int nt = 0; nt < 8; nt++)
                #pragma unroll
                for (int jj = 0; jj < 4; jj++) acc[nt][jj] = 0.f;
            #pragma unroll
            for (int ks = 0; ks < 4; ks++) {
                #pragma unroll
                for (int p = 0; p < 4; p++) {
                    uint32_t bh_[4], bl_[4];
                    uint32_t ka = kaddr + p * 2304 + ks * 32;
                    ldsm_x4(bh_, ka);
                    ldsm_x4(bl_, ka + 9216);
                    mma16816(acc[2*p],     qfh[ks], bh_);
                    mma16816(acc[2*p],     qfl[ks], bh_);
                    mma16816(acc[2*p],     qfh[ks], bl_);
                    mma16816(acc[2*p + 1], qfh[ks], bh_ + 2);
                    mma16816(acc[2*p + 1], qfl[ks], bh_ + 2);
                    mma16816(acc[2*p + 1], qfh[ks], bl_ + 2);
                }
            }

            // ---- exp, normalize, store p ----
            const int* mskj = (const int*)(smem + S_MSK + (j & 1) * 256);
            const int kt0 = j * TK;
            const bool dtile = (j >= 2 * qt);
            float* rowa = attnrow + (size_t)(m0w + g) * SEQ + kt0;
            float* rowb = rowa + (size_t)8 * SEQ;
            #pragma unroll
            for (int nt = 0; nt < 8; nt++) {
                int lc = nt * 8 + t2, gc = kt0 + lc;
                bool k0 = mskj[lc] != 0, k1 = mskj[lc + 1] != 0;
                float e0 = (k0 && (!dtile || gc     <= ra)) ? ex2(acc[nt][0]) : 0.f;
                float e1 = (k1 && (!dtile || gc + 1 <= ra)) ? ex2(acc[nt][1]) : 0.f;
                float e2 = (k0 && (!dtile || gc     <= rb)) ? ex2(acc[nt][2]) : 0.f;
                float e3 = (k1 && (!dtile || gc + 1 <= rb)) ? ex2(acc[nt][3]) : 0.f;
                e0 *= il0; e1 *= il0; e2 *= il1; e3 *= il1;
                acc[nt][0] = e0; acc[nt][1] = e1; acc[nt][2] = e2; acc[nt][3] = e3;
                *(float2*)(rowa + lc) = make_float2(e0, e1);
                *(float2*)(rowb + lc) = make_float2(e2, e3);
            }

            // ---- P·V with normalized p fragments ----
            #pragma unroll
            for (int ks = 0; ks < 4; ks++) {
                uint32_t eh[4], el[4];
                pack_split(acc[2*ks][0],     acc[2*ks][1],     eh[0], el[0]);
                pack_split(acc[2*ks][2],     acc[2*ks][3],     eh[1], el[1]);
                pack_split(acc[2*ks + 1][0], acc[2*ks + 1][1], eh[2], el[2]);
                pack_split(acc[2*ks + 1][2], acc[2*ks + 1][3], eh[3], el[3]);
                #pragma unroll
                for (int p = 0; p < 4; p++) {
                    uint32_t vh_[4], vl_[4];
                    uint32_t va = vaddr + ks * 2304 + p * 32;
                    ldsm_x4t(vh_, va);
                    ldsm_x4t(vl_, va + 9216);
                    mma16816(acc_o[2*p],     eh, vh_);
                    mma16816(acc_o[2*p],     el, vh_);
                    mma16816(acc_o[2*p],     eh, vl_);
                    mma16816(acc_o[2*p + 1], eh, vh_ + 2);
                    mma16816(acc_o[2*p + 1], el, vh_ + 2);
                    mma16816(acc_o[2*p + 1], eh, vl_ + 2);
                }
            }
        }

        // ---- out = acc_o (already normalized) ----
        float* obase = out + ((size_t)bh * SEQ + (size_t)qt * TILE) * HDIM;
        #pragma unroll
        for (int nt = 0; nt < 8; nt++) {
            int c = nt * 8 + t2;
            *(float2*)&obase[(size_t)(m0w + g) * HDIM + c] =
                make_float2(acc_o[nt][0], acc_o[nt][1]);
            *(float2*)&obase[(size_t)(m0w + g + 8) * HDIM + c] =
                make_float2(acc_o[nt][2], acc_o[nt][3]);
        }
        __syncthreads();   // smem (invl/stage) reuse safety between halves
    }
}

// ---------------------------------------------------------------------------
extern "C" void kernel_launch(void* const* d_in, const int* in_sizes, int n_in,
                              void* d_out, int out_size)
{
    const float* q    = (const float*)d_in[0];
    const float* k    = (const float*)d_in[1];
    const float* v    = (const float*)d_in[2];
    const int*   mask = (const int*)d_in[3];

    float* out  = (float*)d_out;                       // [B,H,S,D]
    float* attn = out + (size_t)BH * SEQ * HDIM;       // [B,H,S,S]

    cudaFuncSetAttribute(fused_attn, cudaFuncAttributeMaxDynamicSharedMemorySize, S_SZ);

    prep<<<NELEM / 8 / 256, 256>>>(q, k, v);
    dim3 grid(NT / 2, BH);
    fused_attn<<<grid, 256, S_SZ>>>(mask, out, attn);
}

// round 9
// speedup vs baseline: 2.9422x; 1.1168x over previous
#include <cuda_runtime.h>
#include <cuda_bf16.h>
#include <cstdint>

// B=2,H=16,S=2048,D=64 fp32 causal attention; d_out = out[B,H,S,D] ++ attn[B,H,S,S]
#define SEQ   2048
#define HDIM  64
#define BH    32
#define TILE  128               // q-tile rows per CTA iteration
#define TK    64                // kv-tile rows per pipeline step
#define NT    (SEQ / TILE)      // 16
#define NELEM (BH * SEQ * HDIM) // 4,194,304

// q pre-scale: 1/temperature * log2(e)  (epilogue uses ex2)
#define QSCALE (0.125f * 1.44269504088896341f)

// precomputed bf16 hi/lo splits (prep kernel fills these)
__device__ __align__(16) __nv_bfloat16 g_qh[NELEM];
__device__ __align__(16) __nv_bfloat16 g_ql[NELEM];
__device__ __align__(16) __nv_bfloat16 g_kh[NELEM];
__device__ __align__(16) __nv_bfloat16 g_kl[NELEM];
__device__ __align__(16) __nv_bfloat16 g_vh[NELEM];
__device__ __align__(16) __nv_bfloat16 g_vl[NELEM];

// smem: 2 stages of 55296 B.
//  pass1 stage: KH +0 (64x144B), KL +9216
//  pass2 stage: E  +0 (128 rows x 288B fp32), VH +36864, VL +46080
#define STG_SZ 55296
#define S_MSK  110592           // 2 x 256B (double buffered)
#define S_INV  111104           // 128 floats
#define S_SZ   111616

// ---------------------------------------------------------------------------
__device__ __forceinline__ uint32_t smem_u32(const void* p) {
    uint32_t a;
    asm("{ .reg .u64 t; cvta.to.shared.u64 t, %1; cvt.u32.u64 %0, t; }" : "=r"(a) : "l"(p));
    return a;
}
__device__ __forceinline__ void ldsm_x4(uint32_t* r, uint32_t a) {
    asm volatile("ldmatrix.sync.aligned.m8n8.x4.shared.b16 {%0,%1,%2,%3}, [%4];"
        : "=r"(r[0]), "=r"(r[1]), "=r"(r[2]), "=r"(r[3]) : "r"(a));
}
__device__ __forceinline__ void ldsm_x4t(uint32_t* r, uint32_t a) {
    asm volatile("ldmatrix.sync.aligned.m8n8.x4.trans.shared.b16 {%0,%1,%2,%3}, [%4];"
        : "=r"(r[0]), "=r"(r[1]), "=r"(r[2]), "=r"(r[3]) : "r"(a));
}
__device__ __forceinline__ void mma16816(float* c, const uint32_t* a, const uint32_t* b) {
    asm volatile("mma.sync.aligned.m16n8k16.row.col.f32.bf16.bf16.f32 "
        "{%0,%1,%2,%3}, {%4,%5,%6,%7}, {%8,%9}, {%0,%1,%2,%3};"
        : "+f"(c[0]), "+f"(c[1]), "+f"(c[2]), "+f"(c[3])
        : "r"(a[0]), "r"(a[1]), "r"(a[2]), "r"(a[3]), "r"(b[0]), "r"(b[1]));
}
__device__ __forceinline__ void cp16(uint32_t s, const void* g) {
    asm volatile("cp.async.cg.shared.global [%0], [%1], 16;" :: "r"(s), "l"(g));
}
#define CP_COMMIT() asm volatile("cp.async.commit_group;" ::: "memory")
#define CP_WAIT0()  asm volatile("cp.async.wait_group 0;" ::: "memory")

__device__ __forceinline__ float ex2(float x) {
    float y; asm("ex2.approx.f32 %0, %1;" : "=f"(y) : "f"(x)); return y;
}
__device__ __forceinline__ void pack_split(float x, float y, uint32_t& h, uint32_t& l) {
    __nv_bfloat16 hx = __float2bfloat16(x), hy = __float2bfloat16(y);
    __nv_bfloat162 hv; hv.x = hx; hv.y = hy;
    __nv_bfloat162 lv;
    lv.x = __float2bfloat16(x - __bfloat162float(hx));
    lv.y = __float2bfloat16(y - __bfloat162float(hy));
    h = *reinterpret_cast<uint32_t*>(&hv);
    l = *reinterpret_cast<uint32_t*>(&lv);
}

// ---------------------------------------------------------------------------
// Preprocess: split q (scaled), k, v into bf16 hi/lo global buffers.
// ---------------------------------------------------------------------------
__global__ void __launch_bounds__(256)
prep(const float* __restrict__ q, const float* __restrict__ k,
     const float* __restrict__ v)
{
    size_t i = ((size_t)blockIdx.x * 256 + threadIdx.x) * 8;
    {
        float4 a = *(const float4*)(q + i), b = *(const float4*)(q + i + 4);
        a.x *= QSCALE; a.y *= QSCALE; a.z *= QSCALE; a.w *= QSCALE;
        b.x *= QSCALE; b.y *= QSCALE; b.z *= QSCALE; b.w *= QSCALE;
        uint4 h, l;
        pack_split(a.x, a.y, h.x, l.x); pack_split(a.z, a.w, h.y, l.y);
        pack_split(b.x, b.y, h.z, l.z); pack_split(b.z, b.w, h.w, l.w);
        *(uint4*)(g_qh + i) = h; *(uint4*)(g_ql + i) = l;
    }
    {
        float4 a = *(const float4*)(k + i), b = *(const float4*)(k + i + 4);
        uint4 h, l;
        pack_split(a.x, a.y, h.x, l.x); pack_split(a.z, a.w, h.y, l.y);
        pack_split(b.x, b.y, h.z, l.z); pack_split(b.z, b.w, h.w, l.w);
        *(uint4*)(g_kh + i) = h; *(uint4*)(g_kl + i) = l;
    }
    {
        float4 a = *(const float4*)(v + i), b = *(const float4*)(v + i + 4);
        uint4 h, l;
        pack_split(a.x, a.y, h.x, l.x); pack_split(a.z, a.w, h.y, l.y);
        pack_split(b.x, b.y, h.z, l.z); pack_split(b.z, b.w, h.w, l.w);
        *(uint4*)(g_vh + i) = h; *(uint4*)(g_vl + i) = l;
    }
}

// load a 64x64 bf16 tile (row = 128B contiguous) into smem, 144B row stride
#define LOADT(dstbase, gsrc) do { \
    const char* _g = (const char*)(gsrc); \
    _Pragma("unroll") \
    for (int _t = 0; _t < 2; _t++) { \
        int _i = tid + _t * 256, _r = _i >> 3, _c = _i & 7; \
        cp16((dstbase) + _r * 144 + _c * 16, _g + _r * 128 + _c * 16); \
    } \
} while (0)

// load a 128x64 fp32 e tile (gmem row stride SEQ) into smem, 288B row stride
#define LOADE(dstbase, gsrc) do { \
    const char* _g = (const char*)(gsrc); \
    _Pragma("unroll") \
    for (int _t = 0; _t < 8; _t++) { \
        int _i = tid + _t * 256, _r = _i >> 4, _c = _i & 15; \
        cp16((dstbase) + _r * 288 + _c * 16, _g + (size_t)_r * (SEQ * 4) + _c * 16); \
    } \
} while (0)

// ---------------------------------------------------------------------------
// Fused causal attention, triangle-paired (qt = NT-1-bx then bx).
// Pass 1: QK^T + exp -> store unnormalized e + rowsums.
// Pass 2: reload e via cp.async, normalize, store p, P.V (no QK recompute).
// 256 thr = 8 warps, warp tile 16 x 64. Q fragments register-resident.
// ---------------------------------------------------------------------------
__global__ void __launch_bounds__(256, 2)
fused_attn(const int* __restrict__ mask, float* __restrict__ out,
           float* __restrict__ attn)
{
    extern __shared__ char smem[];
    const int bh  = blockIdx.y, b = bh >> 4;
    const int tid = threadIdx.x, wid = tid >> 5, lane = tid & 31;
    const int g = lane >> 2, t2 = (lane & 3) << 1;
    const int m0w = wid * 16;

    float* invl = (float*)(smem + S_INV);
    const uint32_t sb = smem_u32(smem);

    const uint32_t koff = (uint32_t)((((lane & 7) + ((lane >> 4) & 1) * 8) * 72
                                     + ((lane >> 3) & 1) * 8) * 2);
    const uint32_t voff = (uint32_t)(((lane & 15) * 72 + ((lane >> 4) & 1) * 8) * 2);

    const int* mrow = mask + b * SEQ;
    const size_t plane = (size_t)bh * SEQ * HDIM;

    #pragma unroll 1
    for (int half = 0; half < 2; half++) {
        const int qt = half == 0 ? (NT - 1) - blockIdx.x : blockIdx.x;
        const int nkt = 2 * qt + 2;
        float* attnrow = attn + (size_t)bh * SEQ * SEQ + (size_t)qt * TILE * SEQ;

        // ---- 0) zero the strictly-upper tiles (drains under compute) ----
        {
            const int zc0 = ((qt + 1) * TILE) >> 2;
            const float4 z = make_float4(0.f, 0.f, 0.f, 0.f);
            float4* zbase = (float4*)attnrow;
            for (int r = tid >> 3; r < TILE; r += 32) {
                float4* rowp = zbase + (size_t)r * (SEQ / 4);
                for (int c = zc0 + (lane & 7); c < SEQ / 4; c += 8)
                    rowp[c] = z;
            }
        }

        // ---- 1) prologue: load Q tile into stage area, hoist fragments ----
        uint32_t qfh[4][4], qfl[4][4];
        {
            const char* gq = (const char*)(g_qh + plane + (size_t)qt * TILE * HDIM);
            const char* gl = (const char*)(g_ql + plane + (size_t)qt * TILE * HDIM);
            #pragma unroll
            for (int t = 0; t < 4; t++) {
                int i = tid + t * 256, r = i >> 3, c = i & 7;
                cp16(sb + r * 144 + c * 16,         gq + r * 128 + c * 16);
                cp16(sb + 18432 + r * 144 + c * 16, gl + r * 128 + c * 16);
            }
            CP_COMMIT();
            CP_WAIT0();
            __syncthreads();
            const uint32_t qaddr = sb +
                (uint32_t)(((m0w + (lane & 15)) * 72 + ((lane >> 4) & 1) * 8) * 2);
            #pragma unroll
            for (int ks = 0; ks < 4; ks++) {
                ldsm_x4(qfh[ks], qaddr + ks * 32);
                ldsm_x4(qfl[ks], qaddr + 18432 + ks * 32);
            }
            __syncthreads();   // stage area reusable
        }

        const int ra = qt * TILE + m0w + g, rb = ra + 8;
        float rs0 = 0.f, rs1 = 0.f;

        // ====== PASS 1: QK^T + exp, store unnormalized e, rowsums =========
        LOADT(sb, g_kh + plane);
        LOADT(sb + 9216, g_kl + plane);
        if (tid < 16) cp16(sb + S_MSK + tid * 16, mrow + tid * 4);
        CP_COMMIT();

        for (int j = 0; j < nkt; ++j) {
            CP_WAIT0();
            __syncthreads();
            if (j + 1 < nkt) {
                const uint32_t st1 = sb + ((j + 1) & 1) * STG_SZ;
                const size_t tb = plane + (size_t)(j + 1) * TK * HDIM;
                LOADT(st1, g_kh + tb);
                LOADT(st1 + 9216, g_kl + tb);
                if (tid < 16)
                    cp16(sb + S_MSK + ((j + 1) & 1) * 256 + tid * 16,
                         mrow + (j + 1) * TK + tid * 4);
                CP_COMMIT();
            }
            const uint32_t kaddr = sb + (j & 1) * STG_SZ + koff;

            float acc[8][4];
            #pragma unroll
            for (int nt = 0; nt < 8; nt++)
                #pragma unroll
                for (int jj = 0; jj < 4; jj++) acc[nt][jj] = 0.f;
            #pragma unroll
            for (int ks = 0; ks < 4; ks++) {
                #pragma unroll
                for (int p = 0; p < 4; p++) {
                    uint32_t bh_[4], bl_[4];
                    uint32_t ka = kaddr + p * 2304 + ks * 32;
                    ldsm_x4(bh_, ka);
                    ldsm_x4(bl_, ka + 9216);
                    mma16816(acc[2*p],     qfh[ks], bh_);
                    mma16816(acc[2*p],     qfl[ks], bh_);
                    mma16816(acc[2*p],     qfh[ks], bl_);
                    mma16816(acc[2*p + 1], qfh[ks], bh_ + 2);
                    mma16816(acc[2*p + 1], qfl[ks], bh_ + 2);
                    mma16816(acc[2*p + 1], qfh[ks], bl_ + 2);
                }
            }

            const int* mskj = (const int*)(smem + S_MSK + (j & 1) * 256);
            const int kt0 = j * TK;
            const bool dtile = (j >= 2 * qt);
            float* rowa = attnrow + (size_t)(m0w + g) * SEQ + kt0;
            float* rowb = rowa + (size_t)8 * SEQ;
            #pragma unroll
            for (int nt = 0; nt < 8; nt++) {
                int lc = nt * 8 + t2, gc = kt0 + lc;
                bool k0 = mskj[lc] != 0, k1 = mskj[lc + 1] != 0;
                float e0 = (k0 && (!dtile || gc     <= ra)) ? ex2(acc[nt][0]) : 0.f;
                float e1 = (k1 && (!dtile || gc + 1 <= ra)) ? ex2(acc[nt][1]) : 0.f;
                float e2 = (k0 && (!dtile || gc     <= rb)) ? ex2(acc[nt][2]) : 0.f;
                float e3 = (k1 && (!dtile || gc + 1 <= rb)) ? ex2(acc[nt][3]) : 0.f;
                rs0 += e0 + e1; rs1 += e2 + e3;
                *(float2*)(rowa + lc) = make_float2(e0, e1);
                *(float2*)(rowb + lc) = make_float2(e2, e3);
            }
        }

        // ---- between passes: preload pass-2 tile 0, reduce rowsums ----
        __syncthreads();   // pass-1 smem reads done AND e stores visible CTA-wide
        LOADE(sb, attnrow);
        LOADT(sb + 36864, g_vh + plane);
        LOADT(sb + 46080, g_vl + plane);
        CP_COMMIT();

        rs0 += __shfl_xor_sync(0xFFFFFFFFu, rs0, 1);
        rs0 += __shfl_xor_sync(0xFFFFFFFFu, rs0, 2);
        rs1 += __shfl_xor_sync(0xFFFFFFFFu, rs1, 1);
        rs1 += __shfl_xor_sync(0xFFFFFFFFu, rs1, 2);
        if ((lane & 3) == 0) {
            invl[m0w + g]     = 1.0f / rs0;
            invl[m0w + g + 8] = 1.0f / rs1;
        }
        __syncthreads();
        const float il0 = invl[m0w + g], il1 = invl[m0w + g + 8];

        float acc_o[8][4];
        #pragma unroll
        for (int nt = 0; nt < 8; nt++)
            #pragma unroll
            for (int jj = 0; jj < 4; jj++) acc_o[nt][jj] = 0.f;

        // ====== PASS 2: reload e, normalize + store p, P.V ================
        for (int j = 0; j < nkt; ++j) {
            CP_WAIT0();
            __syncthreads();
            if (j + 1 < nkt) {
                const uint32_t st1 = sb + ((j + 1) & 1) * STG_SZ;
                const size_t tb = plane + (size_t)(j + 1) * TK * HDIM;
                LOADE(st1, attnrow + (j + 1) * TK);
                LOADT(st1 + 36864, g_vh + tb);
                LOADT(st1 + 46080, g_vl + tb);
                CP_COMMIT();
            }
            const char* stb = smem + (size_t)(j & 1) * STG_SZ;
            const float* esm = (const float*)stb;
            const uint32_t vaddr = sb + (j & 1) * STG_SZ + 36864 + voff;

            const float* er0 = esm + (m0w + g) * 72;       // 288B row stride
            const float* er1 = er0 + 8 * 72;
            float* rowa = attnrow + (size_t)(m0w + g) * SEQ + j * TK;
            float* rowb = rowa + (size_t)8 * SEQ;

            #pragma unroll
            for (int ks = 0; ks < 4; ks++) {
                const int c0 = ks * 16 + t2;
                float2 p00 = *(const float2*)(er0 + c0);
                float2 p10 = *(const float2*)(er1 + c0);
                float2 p01 = *(const float2*)(er0 + c0 + 8);
                float2 p11 = *(const float2*)(er1 + c0 + 8);
                p00.x *= il0; p00.y *= il0; p01.x *= il0; p01.y *= il0;
                p10.x *= il1; p10.y *= il1; p11.x *= il1; p11.y *= il1;
                *(float2*)(rowa + c0)     = p00;
                *(float2*)(rowa + c0 + 8) = p01;
                *(float2*)(rowb + c0)     = p10;
                *(float2*)(rowb + c0 + 8) = p11;

                uint32_t eh[4], el[4];
                pack_split(p00.x, p00.y, eh[0], el[0]);
                pack_split(p10.x, p10.y, eh[1], el[1]);
                pack_split(p01.x, p01.y, eh[2], el[2]);
                pack_split(p11.x, p11.y, eh[3], el[3]);
                #pragma unroll
                for (int p = 0; p < 4; p++) {
                    uint32_t vh_[4], vl_[4];
                    uint32_t va = vaddr + ks * 2304 + p * 32;
                    ldsm_x4t(vh_, va);
                    ldsm_x4t(vl_, va + 9216);
                    mma16816(acc_o[2*p],     eh, vh_);
                    mma16816(acc_o[2*p],     el, vh_);
                    mma16816(acc_o[2*p],     eh, vl_);
                    mma16816(acc_o[2*p + 1], eh, vh_ + 2);
                    mma16816(acc_o[2*p + 1], el, vh_ + 2);
                    mma16816(acc_o[2*p + 1], eh, vl_ + 2);
                }
            }
        }

        // ---- out = acc_o (already normalized) ----
        float* obase = out + ((size_t)bh * SEQ + (size_t)qt * TILE) * HDIM;
        #pragma unroll
        for (int nt = 0; nt < 8; nt++) {
            int c = nt * 8 + t2;
            *(float2*)&obase[(size_t)(m0w + g) * HDIM + c] =
                make_float2(acc_o[nt][0], acc_o[nt][1]);
            *(float2*)&obase[(size_t)(m0w + g + 8) * HDIM + c] =
                make_float2(acc_o[nt][2], acc_o[nt][3]);
        }
        __syncthreads();   // smem reuse safety between halves
    }
}

// ---------------------------------------------------------------------------
extern "C" void kernel_launch(void* const* d_in, const int* in_sizes, int n_in,
                              void* d_out, int out_size)
{
    const float* q    = (const float*)d_in[0];
    const float* k    = (const float*)d_in[1];
    const float* v    = (const float*)d_in[2];
    const int*   mask = (const int*)d_in[3];

    float* out  = (float*)d_out;                       // [B,H,S,D]
    float* attn = out + (size_t)BH * SEQ * HDIM;       // [B,H,S,S]

    cudaFuncSetAttribute(fused_attn, cudaFuncAttributeMaxDynamicSharedMemorySize, S_SZ);

    prep<<<NELEM / 8 / 256, 256>>>(q, k, v);
    dim3 grid(NT / 2, BH);
    fused_attn<<<grid, 256, S_SZ>>>(mask, out, attn);
}